// round 1
// baseline (speedup 1.0000x reference)
#include <cuda_runtime.h>
#include <cuda_bf16.h>
#include <math.h>

// Problem constants
#define BB 8
#define TT 1024
#define CC 768
#define HH 12
#define DD 64
#define M_ROWS (BB * TT)          // 8192
#define N_QKV  (3 * CC)           // 2304

// ---------------------------------------------------------------------------
// Scratch (device globals; runtime allocation is forbidden)
// ---------------------------------------------------------------------------
__device__ float g_qkv[M_ROWS * N_QKV];   // [8192, 2304]
__device__ float g_y[M_ROWS * CC];        // [8192, 768] attention output

// ---------------------------------------------------------------------------
// SGEMM with bias: C[M,N] = A[M,K] @ B[K,N] + bias[N]
// BM=BN=128, BK=16, TM=TN=8, 256 threads. All dims divisible by tiles.
// ---------------------------------------------------------------------------
#define GBM 128
#define GBN 128
#define GBK 16
#define GPAD 132   // padded row length for smem tiles (keeps 16B alignment)

__global__ void __launch_bounds__(256)
gemm_bias_kernel(const float* __restrict__ A, const float* __restrict__ B,
                 const float* __restrict__ bias, float* __restrict__ C,
                 int M, int N, int K)
{
    __shared__ float As[GBK * GPAD];  // transposed: As[k][m]
    __shared__ float Bs[GBK * GPAD];  // natural:    Bs[k][n]

    const int tid = threadIdx.x;
    const int bm = blockIdx.y * GBM;
    const int bn = blockIdx.x * GBN;

    const int trow = (tid / 16) * 8;
    const int tcol = (tid % 16) * 8;

    float acc[8][8];
#pragma unroll
    for (int i = 0; i < 8; i++)
#pragma unroll
        for (int j = 0; j < 8; j++) acc[i][j] = 0.0f;

    for (int k0 = 0; k0 < K; k0 += GBK) {
        // Load A tile (128 x 16) -> As transposed [16][128]
#pragma unroll
        for (int it = 0; it < 2; it++) {
            int idx = tid + it * 256;        // 0..511 float4s
            int r   = idx >> 2;              // 0..127
            int c4  = (idx & 3) * 4;         // 0,4,8,12
            float4 v = *(const float4*)&A[(size_t)(bm + r) * K + k0 + c4];
            As[(c4 + 0) * GPAD + r] = v.x;
            As[(c4 + 1) * GPAD + r] = v.y;
            As[(c4 + 2) * GPAD + r] = v.z;
            As[(c4 + 3) * GPAD + r] = v.w;
        }
        // Load B tile (16 x 128) -> Bs [16][128]
#pragma unroll
        for (int it = 0; it < 2; it++) {
            int idx = tid + it * 256;        // 0..511 float4s
            int r   = idx >> 5;              // 0..15
            int c4  = (idx & 31) * 4;        // 0..124
            *(float4*)&Bs[r * GPAD + c4] =
                *(const float4*)&B[(size_t)(k0 + r) * N + bn + c4];
        }
        __syncthreads();

#pragma unroll
        for (int k = 0; k < GBK; k++) {
            float4 a0 = *(const float4*)&As[k * GPAD + trow];
            float4 a1 = *(const float4*)&As[k * GPAD + trow + 4];
            float4 b0 = *(const float4*)&Bs[k * GPAD + tcol];
            float4 b1 = *(const float4*)&Bs[k * GPAD + tcol + 4];
            float ar[8] = {a0.x, a0.y, a0.z, a0.w, a1.x, a1.y, a1.z, a1.w};
            float br[8] = {b0.x, b0.y, b0.z, b0.w, b1.x, b1.y, b1.z, b1.w};
#pragma unroll
            for (int i = 0; i < 8; i++)
#pragma unroll
                for (int j = 0; j < 8; j++)
                    acc[i][j] += ar[i] * br[j];
        }
        __syncthreads();
    }

    // Epilogue: add bias, write
#pragma unroll
    for (int i = 0; i < 8; i++) {
#pragma unroll
        for (int j4 = 0; j4 < 8; j4 += 4) {
            float4 o;
            o.x = acc[i][j4 + 0] + bias[bn + tcol + j4 + 0];
            o.y = acc[i][j4 + 1] + bias[bn + tcol + j4 + 1];
            o.z = acc[i][j4 + 2] + bias[bn + tcol + j4 + 2];
            o.w = acc[i][j4 + 3] + bias[bn + tcol + j4 + 3];
            *(float4*)&C[(size_t)(bm + trow + i) * N + bn + tcol + j4] = o;
        }
    }
}

// ---------------------------------------------------------------------------
// Fused causal flash attention (fp32).
// Q/K/V are strided views into g_qkv: row stride 2304, head offset h*64,
// K at +768, V at +1536.
// Block: 64 query rows for one (b,h). 256 threads, 4x4 microtile over 64x64.
// Online softmax; P staged through smem for the PV GEMM.
// ---------------------------------------------------------------------------
#define APAD 68  // padded row length (floats), keeps float4 alignment

__global__ void __launch_bounds__(256)
attn_kernel(const float* __restrict__ qkv, float* __restrict__ y)
{
    extern __shared__ float sm[];
    float* Qs = sm;                 // [64][68] transposed: Qs[d][r]
    float* Ks = Qs + 64 * APAD;     // [64][68] transposed: Ks[d][j]
    float* Vs = Ks + 64 * APAD;     // [64][68] natural:    Vs[j][d]
    float* Ps = Vs + 64 * APAD;     // [64][68] natural:    Ps[i][j]

    const int qt  = blockIdx.x;     // query tile 0..15
    const int bh  = blockIdx.y;     // 0..95
    const int b   = bh / HH;
    const int h   = bh % HH;
    const int q0  = qt * 64;
    const int tid = threadIdx.x;
    const int trow = (tid / 16) * 4;
    const int tcol = (tid % 16) * 4;

    const float* qbase = qkv + (size_t)b * TT * N_QKV + h * DD;
    const float* kbase = qbase + CC;
    const float* vbase = qbase + 2 * CC;
    const float scale = 0.125f;     // 1/sqrt(64)

    // Load Q tile, transposed + pre-scaled
    {
        int r  = tid / 16;
        int c4 = (tid % 16) * 4;
        for (int rr = r; rr < 64; rr += 16) {
            float4 v = *(const float4*)&qbase[(size_t)(q0 + rr) * N_QKV + c4];
            Qs[(c4 + 0) * APAD + rr] = v.x * scale;
            Qs[(c4 + 1) * APAD + rr] = v.y * scale;
            Qs[(c4 + 2) * APAD + rr] = v.z * scale;
            Qs[(c4 + 3) * APAD + rr] = v.w * scale;
        }
    }

    float m[4], l[4], o[4][4];
#pragma unroll
    for (int i = 0; i < 4; i++) {
        m[i] = -1e30f; l[i] = 0.0f;
#pragma unroll
        for (int j = 0; j < 4; j++) o[i][j] = 0.0f;
    }

    for (int kt = 0; kt <= qt; kt++) {
        const int k0 = kt * 64;
        __syncthreads();   // previous PV reads (Vs/Ps) done; also orders Q load

        // Load K (transposed) and V (natural) tiles
        {
            int r  = tid / 16;
            int c4 = (tid % 16) * 4;
            for (int rr = r; rr < 64; rr += 16) {
                float4 kv = *(const float4*)&kbase[(size_t)(k0 + rr) * N_QKV + c4];
                Ks[(c4 + 0) * APAD + rr] = kv.x;
                Ks[(c4 + 1) * APAD + rr] = kv.y;
                Ks[(c4 + 2) * APAD + rr] = kv.z;
                Ks[(c4 + 3) * APAD + rr] = kv.w;
                float4 vv = *(const float4*)&vbase[(size_t)(k0 + rr) * N_QKV + c4];
                *(float4*)&Vs[rr * APAD + c4] = vv;
            }
        }
        __syncthreads();

        // S = (Q*scale) K^T, 4x4 per thread
        float s[4][4];
#pragma unroll
        for (int i = 0; i < 4; i++)
#pragma unroll
            for (int j = 0; j < 4; j++) s[i][j] = 0.0f;

#pragma unroll 8
        for (int d = 0; d < 64; d++) {
            float4 a  = *(const float4*)&Qs[d * APAD + trow];
            float4 bb = *(const float4*)&Ks[d * APAD + tcol];
            float ar[4] = {a.x, a.y, a.z, a.w};
            float br[4] = {bb.x, bb.y, bb.z, bb.w};
#pragma unroll
            for (int i = 0; i < 4; i++)
#pragma unroll
                for (int j = 0; j < 4; j++)
                    s[i][j] += ar[i] * br[j];
        }

        // Causal mask (diagonal tile only)
        if (kt == qt) {
#pragma unroll
            for (int i = 0; i < 4; i++)
#pragma unroll
                for (int j = 0; j < 4; j++)
                    if (tcol + j > trow + i) s[i][j] = -1e30f;
        }

        // Online softmax. Row group = 16 consecutive lanes (shfl width 16).
#pragma unroll
        for (int i = 0; i < 4; i++) {
            float rmax = fmaxf(fmaxf(s[i][0], s[i][1]), fmaxf(s[i][2], s[i][3]));
            rmax = fmaxf(rmax, __shfl_xor_sync(0xffffffffu, rmax, 1));
            rmax = fmaxf(rmax, __shfl_xor_sync(0xffffffffu, rmax, 2));
            rmax = fmaxf(rmax, __shfl_xor_sync(0xffffffffu, rmax, 4));
            rmax = fmaxf(rmax, __shfl_xor_sync(0xffffffffu, rmax, 8));
            float mnew = fmaxf(m[i], rmax);
            float corr = __expf(m[i] - mnew);
            float rs = 0.0f;
#pragma unroll
            for (int j = 0; j < 4; j++) {
                s[i][j] = __expf(s[i][j] - mnew);
                rs += s[i][j];
            }
            rs += __shfl_xor_sync(0xffffffffu, rs, 1);
            rs += __shfl_xor_sync(0xffffffffu, rs, 2);
            rs += __shfl_xor_sync(0xffffffffu, rs, 4);
            rs += __shfl_xor_sync(0xffffffffu, rs, 8);
            l[i] = l[i] * corr + rs;
            m[i] = mnew;
#pragma unroll
            for (int j = 0; j < 4; j++) o[i][j] *= corr;
            *(float4*)&Ps[(trow + i) * APAD + tcol] =
                make_float4(s[i][0], s[i][1], s[i][2], s[i][3]);
        }
        __syncthreads();

        // O += P @ V
#pragma unroll 8
        for (int jj = 0; jj < 64; jj++) {
            float4 vv = *(const float4*)&Vs[jj * APAD + tcol];
            float vr[4] = {vv.x, vv.y, vv.z, vv.w};
            float pr[4];
#pragma unroll
            for (int i = 0; i < 4; i++) pr[i] = Ps[(trow + i) * APAD + jj];
#pragma unroll
            for (int i = 0; i < 4; i++)
#pragma unroll
                for (int j = 0; j < 4; j++)
                    o[i][j] += pr[i] * vr[j];
        }
    }

    // Normalize and write y[b][t][h*64 + d]
#pragma unroll
    for (int i = 0; i < 4; i++) {
        float inv = 1.0f / l[i];
        float4 ov = make_float4(o[i][0] * inv, o[i][1] * inv,
                                o[i][2] * inv, o[i][3] * inv);
        *(float4*)&y[(size_t)(b * TT + q0 + trow + i) * CC + h * DD + tcol] = ov;
    }
}

// ---------------------------------------------------------------------------
// Launch
// ---------------------------------------------------------------------------
extern "C" void kernel_launch(void* const* d_in, const int* in_sizes, int n_in,
                              void* d_out, int out_size)
{
    const float* x     = (const float*)d_in[0];  // [8,1024,768]
    const float* wqkv  = (const float*)d_in[1];  // [768, 2304]
    const float* bqkv  = (const float*)d_in[2];  // [2304]
    const float* wproj = (const float*)d_in[3];  // [768, 768]
    const float* bproj = (const float*)d_in[4];  // [768]
    float* out = (float*)d_out;                  // [8,1024,768]

    float* qkv = nullptr;
    float* y   = nullptr;
    cudaGetSymbolAddress((void**)&qkv, g_qkv);
    cudaGetSymbolAddress((void**)&y, g_y);

    // 1) qkv = x @ Wqkv + b      M=8192, N=2304, K=768
    gemm_bias_kernel<<<dim3(N_QKV / GBN, M_ROWS / GBM), 256>>>(
        x, wqkv, bqkv, qkv, M_ROWS, N_QKV, CC);

    // 2) fused causal attention -> y
    const int attn_smem = 4 * 64 * APAD * (int)sizeof(float);  // 69632 B
    cudaFuncSetAttribute(attn_kernel,
                         cudaFuncAttributeMaxDynamicSharedMemorySize, attn_smem);
    attn_kernel<<<dim3(TT / 64, BB * HH), 256, attn_smem>>>(qkv, y);

    // 3) out = y @ Wproj + b     M=8192, N=768, K=768
    gemm_bias_kernel<<<dim3(CC / GBN, M_ROWS / GBM), 256>>>(
        y, wproj, bproj, out, M_ROWS, CC, CC);
}

// round 9
// speedup vs baseline: 1.5172x; 1.5172x over previous
#include <cuda_runtime.h>
#include <cuda_bf16.h>
#include <cstdint>
#include <math.h>

// Problem constants
#define BB 8
#define TT 1024
#define CC 768
#define HH 12
#define DD 64
#define M_ROWS (BB * TT)          // 8192
#define N_QKV  (3 * CC)           // 2304

// ---------------------------------------------------------------------------
// Scratch (device globals; runtime allocation is forbidden)
// ---------------------------------------------------------------------------
__device__ float g_qkv[M_ROWS * N_QKV];            // [8192, 2304] fp32
__device__ __nv_bfloat16 g_x_hi[M_ROWS * CC];
__device__ __nv_bfloat16 g_x_lo[M_ROWS * CC];
__device__ __nv_bfloat16 g_wq_hi[N_QKV * CC];      // Wqkv^T [2304][768]
__device__ __nv_bfloat16 g_wq_lo[N_QKV * CC];
__device__ __nv_bfloat16 g_wp_hi[CC * CC];         // Wproj^T [768][768]
__device__ __nv_bfloat16 g_wp_lo[CC * CC];
__device__ __nv_bfloat16 g_y_hi[M_ROWS * CC];      // attention out split
__device__ __nv_bfloat16 g_y_lo[M_ROWS * CC];

// ---------------------------------------------------------------------------
// Portable (non-'a') tensor-core helpers: mma.sync + ldmatrix + cp.async
// ---------------------------------------------------------------------------
__device__ __forceinline__ uint32_t smem_u32(const void* p) {
    uint32_t a;
    asm("{ .reg .u64 t; cvta.to.shared.u64 t, %1; cvt.u32.u64 %0, t; }"
        : "=r"(a) : "l"(p));
    return a;
}

#define CP_ASYNC16(dst, src) \
    asm volatile("cp.async.cg.shared.global [%0], [%1], 16;" \
                 :: "r"(dst), "l"(src) : "memory")
#define CP_COMMIT() asm volatile("cp.async.commit_group;" ::: "memory")
#define CP_WAIT(n)  asm volatile("cp.async.wait_group %0;" :: "n"(n) : "memory")

#define LDSM_X4(r0, r1, r2, r3, addr) \
    asm volatile("ldmatrix.sync.aligned.m8n8.x4.shared.b16 {%0,%1,%2,%3}, [%4];" \
                 : "=r"(r0), "=r"(r1), "=r"(r2), "=r"(r3) : "r"(addr))
#define LDSM_X2(r0, r1, addr) \
    asm volatile("ldmatrix.sync.aligned.m8n8.x2.shared.b16 {%0,%1}, [%2];" \
                 : "=r"(r0), "=r"(r1) : "r"(addr))

__device__ __forceinline__ void mma_bf16(float* c, const uint32_t* a, const uint32_t* b) {
    asm volatile(
        "mma.sync.aligned.m16n8k16.row.col.f32.bf16.bf16.f32 "
        "{%0,%1,%2,%3}, {%4,%5,%6,%7}, {%8,%9}, {%0,%1,%2,%3};"
        : "+f"(c[0]), "+f"(c[1]), "+f"(c[2]), "+f"(c[3])
        : "r"(a[0]), "r"(a[1]), "r"(a[2]), "r"(a[3]), "r"(b[0]), "r"(b[1]));
}

// ---------------------------------------------------------------------------
// Split-bf16 HMMA GEMM: C[M,N] = A[M,K] @ W + bias  (W given transposed
// as B[N,K]).  3-term split: Ahi*Bhi + Ahi*Blo + Alo*Bhi, fp32 reg accum.
// CTA 128x128, BK=32, 8 warps of 64x32, cp.async double buffering.
// ---------------------------------------------------------------------------
#define PITCH 40                          // bf16 elems per smem row (32 + 8 pad)
#define TILE_B (128 * PITCH * 2)          // 10240 bytes per tile
#define STAGE_B (4 * TILE_B)              // Ahi|Alo|Bhi|Blo = 40960
#define GEMM_SMEM (2 * STAGE_B)           // 81920

__global__ void __launch_bounds__(256, 1)
mma_gemm_kernel(const __nv_bfloat16* __restrict__ Ahi,
                const __nv_bfloat16* __restrict__ Alo,
                const __nv_bfloat16* __restrict__ Bhi,
                const __nv_bfloat16* __restrict__ Blo,
                const float* __restrict__ bias, float* __restrict__ C,
                int M, int N, int K)
{
    extern __shared__ char smem[];
    const uint32_t sb = smem_u32(smem);
    const int tid = threadIdx.x;
    const int wid = tid >> 5;
    const int lid = tid & 31;
    const int bm = blockIdx.y * 128;
    const int bn = blockIdx.x * 128;
    const int m0 = (wid >> 2) * 64;       // warp M offset (0 or 64)
    const int n0 = (wid & 3) * 32;        // warp N offset
    const int NCH = K / 32;

    float acc[4][4][4];
#pragma unroll
    for (int i = 0; i < 4; i++)
#pragma unroll
        for (int j = 0; j < 4; j++)
#pragma unroll
            for (int r = 0; r < 4; r++) acc[i][j][r] = 0.0f;

    // ---- async tile loader: 128 rows x 32 bf16 (= 512 x 16B) ----
    auto cp_tile = [&](const __nv_bfloat16* g, int row0, int kc, uint32_t sdst) {
#pragma unroll
        for (int it = 0; it < 2; ++it) {
            int idx = tid + it * 256;     // 0..511
            int r = idx >> 2;
            int u = idx & 3;
            const __nv_bfloat16* src = g + (size_t)(row0 + r) * K + kc + u * 8;
            uint32_t dst = sdst + (r * PITCH + u * 8) * 2;
            CP_ASYNC16(dst, src);
        }
    };
    auto load_stage = [&](int c, int stg) {
        uint32_t base = sb + stg * STAGE_B;
        int kc = c * 32;
        cp_tile(Ahi, bm, kc, base);
        cp_tile(Alo, bm, kc, base + TILE_B);
        cp_tile(Bhi, bn, kc, base + 2 * TILE_B);
        cp_tile(Blo, bn, kc, base + 3 * TILE_B);
    };

    load_stage(0, 0);
    CP_COMMIT();

    const int a_row = lid & 15;
    const int a_k   = lid >> 4;           // 0/1 -> +8 k cols
    const int b_row = lid & 7;
    const int b_k   = (lid >> 3) & 1;

    for (int c = 0; c < NCH; ++c) {
        if (c + 1 < NCH) {
            load_stage(c + 1, (c + 1) & 1);
            CP_COMMIT();
            CP_WAIT(1);
        } else {
            CP_WAIT(0);
        }
        __syncthreads();

        const uint32_t base = sb + (c & 1) * STAGE_B;
        const uint32_t pa_hi = base + ((m0 + a_row) * PITCH + a_k * 8) * 2;
        const uint32_t pa_lo = pa_hi + TILE_B;
        const uint32_t pb_hi = base + 2 * TILE_B + ((n0 + b_row) * PITCH + b_k * 8) * 2;
        const uint32_t pb_lo = pb_hi + TILE_B;

#pragma unroll
        for (int ks = 0; ks < 2; ++ks) {
            const uint32_t ko = ks * 32;  // 16 bf16 = 32 bytes
            uint32_t Ah[4][4], Al[4][4], Bh[4][2], Bl[4][2];
#pragma unroll
            for (int mf = 0; mf < 4; ++mf) {
                uint32_t off = ko + mf * (16 * PITCH * 2);
                LDSM_X4(Ah[mf][0], Ah[mf][1], Ah[mf][2], Ah[mf][3], pa_hi + off);
                LDSM_X4(Al[mf][0], Al[mf][1], Al[mf][2], Al[mf][3], pa_lo + off);
            }
#pragma unroll
            for (int nf = 0; nf < 4; ++nf) {
                uint32_t off = ko + nf * (8 * PITCH * 2);
                LDSM_X2(Bh[nf][0], Bh[nf][1], pb_hi + off);
                LDSM_X2(Bl[nf][0], Bl[nf][1], pb_lo + off);
            }
#pragma unroll
            for (int mf = 0; mf < 4; ++mf)
#pragma unroll
                for (int nf = 0; nf < 4; ++nf) {
                    mma_bf16(acc[mf][nf], Ah[mf], Bh[nf]);
                    mma_bf16(acc[mf][nf], Ah[mf], Bl[nf]);
                    mma_bf16(acc[mf][nf], Al[mf], Bh[nf]);
                }
        }
        __syncthreads();
    }

    // Epilogue: c-frag (row = lid/4 [+8], col = (lid%4)*2) + bias, float2 stores
    const int grow = lid >> 2;
    const int gcol = (lid & 3) * 2;
#pragma unroll
    for (int mf = 0; mf < 4; ++mf) {
#pragma unroll
        for (int nf = 0; nf < 4; ++nf) {
            int r0  = bm + m0 + mf * 16 + grow;
            int col = bn + n0 + nf * 8 + gcol;
            float b0 = bias[col], b1 = bias[col + 1];
            float2 v0 = make_float2(acc[mf][nf][0] + b0, acc[mf][nf][1] + b1);
            float2 v1 = make_float2(acc[mf][nf][2] + b0, acc[mf][nf][3] + b1);
            *(float2*)&C[(size_t)r0 * N + col]       = v0;
            *(float2*)&C[(size_t)(r0 + 8) * N + col] = v1;
        }
    }
}

// ---------------------------------------------------------------------------
// fp32 -> (bf16 hi, bf16 lo) split, vectorized
// ---------------------------------------------------------------------------
__global__ void __launch_bounds__(256)
split_kernel(const float* __restrict__ in, __nv_bfloat16* __restrict__ hi,
             __nv_bfloat16* __restrict__ lo, int n4)
{
    int i = blockIdx.x * blockDim.x + threadIdx.x;
    if (i >= n4) return;
    float4 v = ((const float4*)in)[i];
    __nv_bfloat16 h0 = __float2bfloat16(v.x), h1 = __float2bfloat16(v.y);
    __nv_bfloat16 h2 = __float2bfloat16(v.z), h3 = __float2bfloat16(v.w);
    __nv_bfloat16 l0 = __float2bfloat16(v.x - __bfloat162float(h0));
    __nv_bfloat16 l1 = __float2bfloat16(v.y - __bfloat162float(h1));
    __nv_bfloat16 l2 = __float2bfloat16(v.z - __bfloat162float(h2));
    __nv_bfloat16 l3 = __float2bfloat16(v.w - __bfloat162float(h3));
    __nv_bfloat162 p;
    p.x = h0; p.y = h1; ((__nv_bfloat162*)hi)[2 * i]     = p;
    p.x = h2; p.y = h3; ((__nv_bfloat162*)hi)[2 * i + 1] = p;
    p.x = l0; p.y = l1; ((__nv_bfloat162*)lo)[2 * i]     = p;
    p.x = l2; p.y = l3; ((__nv_bfloat162*)lo)[2 * i + 1] = p;
}

// ---------------------------------------------------------------------------
// W[K][N] fp32 -> T[N][K] bf16 hi/lo (tiled transpose)
// ---------------------------------------------------------------------------
__global__ void __launch_bounds__(256)
transpose_split_kernel(const float* __restrict__ W, __nv_bfloat16* __restrict__ Thi,
                       __nv_bfloat16* __restrict__ Tlo, int K, int N)
{
    __shared__ float t[32][33];
    const int n0 = blockIdx.x * 32;
    const int k0 = blockIdx.y * 32;
    const int tx = threadIdx.x, ty = threadIdx.y;
#pragma unroll
    for (int j = 0; j < 4; ++j)
        t[ty + j * 8][tx] = W[(size_t)(k0 + ty + j * 8) * N + n0 + tx];
    __syncthreads();
#pragma unroll
    for (int j = 0; j < 4; ++j) {
        int n = n0 + ty + j * 8;
        int k = k0 + tx;
        float v = t[tx][ty + j * 8];
        __nv_bfloat16 h = __float2bfloat16(v);
        Thi[(size_t)n * K + k] = h;
        Tlo[(size_t)n * K + k] = __float2bfloat16(v - __bfloat162float(h));
    }
}

// ---------------------------------------------------------------------------
// Fused causal flash attention (fp32), outputs split bf16 hi/lo
// ---------------------------------------------------------------------------
#define APAD 68

__global__ void __launch_bounds__(256)
attn_kernel(const float* __restrict__ qkv, __nv_bfloat16* __restrict__ yhi,
            __nv_bfloat16* __restrict__ ylo)
{
    extern __shared__ float sm[];
    float* Qs = sm;
    float* Ks = Qs + 64 * APAD;
    float* Vs = Ks + 64 * APAD;
    float* Ps = Vs + 64 * APAD;

    const int qt  = blockIdx.x;
    const int bh  = blockIdx.y;
    const int b   = bh / HH;
    const int h   = bh % HH;
    const int q0  = qt * 64;
    const int tid = threadIdx.x;
    const int trow = (tid / 16) * 4;
    const int tcol = (tid % 16) * 4;

    const float* qbase = qkv + (size_t)b * TT * N_QKV + h * DD;
    const float* kbase = qbase + CC;
    const float* vbase = qbase + 2 * CC;
    const float scale = 0.125f;

    {
        int r  = tid / 16;
        int c4 = (tid % 16) * 4;
        for (int rr = r; rr < 64; rr += 16) {
            float4 v = *(const float4*)&qbase[(size_t)(q0 + rr) * N_QKV + c4];
            Qs[(c4 + 0) * APAD + rr] = v.x * scale;
            Qs[(c4 + 1) * APAD + rr] = v.y * scale;
            Qs[(c4 + 2) * APAD + rr] = v.z * scale;
            Qs[(c4 + 3) * APAD + rr] = v.w * scale;
        }
    }

    float m[4], l[4], o[4][4];
#pragma unroll
    for (int i = 0; i < 4; i++) {
        m[i] = -1e30f; l[i] = 0.0f;
#pragma unroll
        for (int j = 0; j < 4; j++) o[i][j] = 0.0f;
    }

    for (int kt = 0; kt <= qt; kt++) {
        const int k0 = kt * 64;
        __syncthreads();
        {
            int r  = tid / 16;
            int c4 = (tid % 16) * 4;
            for (int rr = r; rr < 64; rr += 16) {
                float4 kv = *(const float4*)&kbase[(size_t)(k0 + rr) * N_QKV + c4];
                Ks[(c4 + 0) * APAD + rr] = kv.x;
                Ks[(c4 + 1) * APAD + rr] = kv.y;
                Ks[(c4 + 2) * APAD + rr] = kv.z;
                Ks[(c4 + 3) * APAD + rr] = kv.w;
                float4 vv = *(const float4*)&vbase[(size_t)(k0 + rr) * N_QKV + c4];
                *(float4*)&Vs[rr * APAD + c4] = vv;
            }
        }
        __syncthreads();

        float s[4][4];
#pragma unroll
        for (int i = 0; i < 4; i++)
#pragma unroll
            for (int j = 0; j < 4; j++) s[i][j] = 0.0f;

#pragma unroll 8
        for (int d = 0; d < 64; d++) {
            float4 a  = *(const float4*)&Qs[d * APAD + trow];
            float4 bb = *(const float4*)&Ks[d * APAD + tcol];
            float ar[4] = {a.x, a.y, a.z, a.w};
            float br[4] = {bb.x, bb.y, bb.z, bb.w};
#pragma unroll
            for (int i = 0; i < 4; i++)
#pragma unroll
                for (int j = 0; j < 4; j++)
                    s[i][j] += ar[i] * br[j];
        }

        if (kt == qt) {
#pragma unroll
            for (int i = 0; i < 4; i++)
#pragma unroll
                for (int j = 0; j < 4; j++)
                    if (tcol + j > trow + i) s[i][j] = -1e30f;
        }

#pragma unroll
        for (int i = 0; i < 4; i++) {
            float rmax = fmaxf(fmaxf(s[i][0], s[i][1]), fmaxf(s[i][2], s[i][3]));
            rmax = fmaxf(rmax, __shfl_xor_sync(0xffffffffu, rmax, 1));
            rmax = fmaxf(rmax, __shfl_xor_sync(0xffffffffu, rmax, 2));
            rmax = fmaxf(rmax, __shfl_xor_sync(0xffffffffu, rmax, 4));
            rmax = fmaxf(rmax, __shfl_xor_sync(0xffffffffu, rmax, 8));
            float mnew = fmaxf(m[i], rmax);
            float corr = __expf(m[i] - mnew);
            float rs = 0.0f;
#pragma unroll
            for (int j = 0; j < 4; j++) {
                s[i][j] = __expf(s[i][j] - mnew);
                rs += s[i][j];
            }
            rs += __shfl_xor_sync(0xffffffffu, rs, 1);
            rs += __shfl_xor_sync(0xffffffffu, rs, 2);
            rs += __shfl_xor_sync(0xffffffffu, rs, 4);
            rs += __shfl_xor_sync(0xffffffffu, rs, 8);
            l[i] = l[i] * corr + rs;
            m[i] = mnew;
#pragma unroll
            for (int j = 0; j < 4; j++) o[i][j] *= corr;
            *(float4*)&Ps[(trow + i) * APAD + tcol] =
                make_float4(s[i][0], s[i][1], s[i][2], s[i][3]);
        }
        __syncthreads();

#pragma unroll 8
        for (int jj = 0; jj < 64; jj++) {
            float4 vv = *(const float4*)&Vs[jj * APAD + tcol];
            float vr[4] = {vv.x, vv.y, vv.z, vv.w};
            float pr[4];
#pragma unroll
            for (int i = 0; i < 4; i++) pr[i] = Ps[(trow + i) * APAD + jj];
#pragma unroll
            for (int i = 0; i < 4; i++)
#pragma unroll
                for (int j = 0; j < 4; j++)
                    o[i][j] += pr[i] * vr[j];
        }
    }

    // Normalize and write y as bf16 hi/lo split
#pragma unroll
    for (int i = 0; i < 4; i++) {
        float inv = 1.0f / l[i];
        float v0 = o[i][0] * inv, v1 = o[i][1] * inv;
        float v2 = o[i][2] * inv, v3 = o[i][3] * inv;
        __nv_bfloat16 h0 = __float2bfloat16(v0), h1 = __float2bfloat16(v1);
        __nv_bfloat16 h2 = __float2bfloat16(v2), h3 = __float2bfloat16(v3);
        __nv_bfloat16 l0 = __float2bfloat16(v0 - __bfloat162float(h0));
        __nv_bfloat16 l1 = __float2bfloat16(v1 - __bfloat162float(h1));
        __nv_bfloat16 l2 = __float2bfloat16(v2 - __bfloat162float(h2));
        __nv_bfloat16 l3 = __float2bfloat16(v3 - __bfloat162float(h3));
        size_t base = (size_t)(b * TT + q0 + trow + i) * CC + h * DD + tcol;
        __nv_bfloat162 p;
        p.x = h0; p.y = h1; *(__nv_bfloat162*)&yhi[base]     = p;
        p.x = h2; p.y = h3; *(__nv_bfloat162*)&yhi[base + 2] = p;
        p.x = l0; p.y = l1; *(__nv_bfloat162*)&ylo[base]     = p;
        p.x = l2; p.y = l3; *(__nv_bfloat162*)&ylo[base + 2] = p;
    }
}

// ---------------------------------------------------------------------------
// Launch
// ---------------------------------------------------------------------------
extern "C" void kernel_launch(void* const* d_in, const int* in_sizes, int n_in,
                              void* d_out, int out_size)
{
    const float* x     = (const float*)d_in[0];
    const float* wqkv  = (const float*)d_in[1];
    const float* bqkv  = (const float*)d_in[2];
    const float* wproj = (const float*)d_in[3];
    const float* bproj = (const float*)d_in[4];
    float* out = (float*)d_out;

    float* qkv; __nv_bfloat16 *xh, *xl, *wqh, *wql, *wph, *wpl, *yh, *yl;
    cudaGetSymbolAddress((void**)&qkv, g_qkv);
    cudaGetSymbolAddress((void**)&xh,  g_x_hi);
    cudaGetSymbolAddress((void**)&xl,  g_x_lo);
    cudaGetSymbolAddress((void**)&wqh, g_wq_hi);
    cudaGetSymbolAddress((void**)&wql, g_wq_lo);
    cudaGetSymbolAddress((void**)&wph, g_wp_hi);
    cudaGetSymbolAddress((void**)&wpl, g_wp_lo);
    cudaGetSymbolAddress((void**)&yh,  g_y_hi);
    cudaGetSymbolAddress((void**)&yl,  g_y_lo);

    cudaFuncSetAttribute(mma_gemm_kernel,
                         cudaFuncAttributeMaxDynamicSharedMemorySize, GEMM_SMEM);
    cudaFuncSetAttribute(attn_kernel,
                         cudaFuncAttributeMaxDynamicSharedMemorySize,
                         4 * 64 * APAD * (int)sizeof(float));

    // Prep: split x; transpose+split both weight matrices
    split_kernel<<<(M_ROWS * CC / 4 + 255) / 256, 256>>>(x, xh, xl, M_ROWS * CC / 4);
    transpose_split_kernel<<<dim3(N_QKV / 32, CC / 32), dim3(32, 8)>>>(wqkv, wqh, wql, CC, N_QKV);
    transpose_split_kernel<<<dim3(CC / 32, CC / 32), dim3(32, 8)>>>(wproj, wph, wpl, CC, CC);

    // 1) qkv = x @ Wqkv + b  (HMMA split-bf16)
    mma_gemm_kernel<<<dim3(N_QKV / 128, M_ROWS / 128), 256, GEMM_SMEM>>>(
        xh, xl, wqh, wql, bqkv, qkv, M_ROWS, N_QKV, CC);

    // 2) fused causal attention -> y (split bf16)
    attn_kernel<<<dim3(TT / 64, BB * HH), 256, 4 * 64 * APAD * (int)sizeof(float)>>>(
        qkv, yh, yl);

    // 3) out = y @ Wproj + b  (HMMA split-bf16)
    mma_gemm_kernel<<<dim3(CC / 128, M_ROWS / 128), 256, GEMM_SMEM>>>(
        yh, yl, wph, wpl, bproj, out, M_ROWS, CC, CC);
}

// round 12
// speedup vs baseline: 2.2984x; 1.5149x over previous
#include <cuda_runtime.h>
#include <cuda_bf16.h>
#include <cstdint>
#include <math.h>

// Problem constants
#define BB 8
#define TT 1024
#define CC 768
#define HH 12
#define DD 64
#define M_ROWS (BB * TT)          // 8192
#define N_QKV  (3 * CC)           // 2304

// ---------------------------------------------------------------------------
// Scratch (device globals; runtime allocation is forbidden)
// ---------------------------------------------------------------------------
__device__ __nv_bfloat16 g_qkv_hi[M_ROWS * N_QKV];
__device__ __nv_bfloat16 g_qkv_lo[M_ROWS * N_QKV];
__device__ __nv_bfloat16 g_x_hi[M_ROWS * CC];
__device__ __nv_bfloat16 g_x_lo[M_ROWS * CC];
__device__ __nv_bfloat16 g_wq_hi[N_QKV * CC];      // Wqkv^T [2304][768]
__device__ __nv_bfloat16 g_wq_lo[N_QKV * CC];
__device__ __nv_bfloat16 g_wp_hi[CC * CC];         // Wproj^T [768][768]
__device__ __nv_bfloat16 g_wp_lo[CC * CC];
__device__ __nv_bfloat16 g_y_hi[M_ROWS * CC];      // attention out split
__device__ __nv_bfloat16 g_y_lo[M_ROWS * CC];

// ---------------------------------------------------------------------------
// Portable tensor-core helpers: mma.sync + ldmatrix + cp.async
// ---------------------------------------------------------------------------
__device__ __forceinline__ uint32_t smem_u32(const void* p) {
    uint32_t a;
    asm("{ .reg .u64 t; cvta.to.shared.u64 t, %1; cvt.u32.u64 %0, t; }"
        : "=r"(a) : "l"(p));
    return a;
}

#define CP_ASYNC16(dst, src) \
    asm volatile("cp.async.cg.shared.global [%0], [%1], 16;" \
                 :: "r"(dst), "l"(src) : "memory")
#define CP_COMMIT() asm volatile("cp.async.commit_group;" ::: "memory")
#define CP_WAIT(n)  asm volatile("cp.async.wait_group %0;" :: "n"(n) : "memory")

#define LDSM_X4(r0, r1, r2, r3, addr) \
    asm volatile("ldmatrix.sync.aligned.m8n8.x4.shared.b16 {%0,%1,%2,%3}, [%4];" \
                 : "=r"(r0), "=r"(r1), "=r"(r2), "=r"(r3) : "r"(addr))
#define LDSM_X2(r0, r1, addr) \
    asm volatile("ldmatrix.sync.aligned.m8n8.x2.shared.b16 {%0,%1}, [%2];" \
                 : "=r"(r0), "=r"(r1) : "r"(addr))
#define LDSM_X2_T(r0, r1, addr) \
    asm volatile("ldmatrix.sync.aligned.m8n8.x2.trans.shared.b16 {%0,%1}, [%2];" \
                 : "=r"(r0), "=r"(r1) : "r"(addr))

__device__ __forceinline__ void mma_bf16(float* c, const uint32_t* a, const uint32_t* b) {
    asm volatile(
        "mma.sync.aligned.m16n8k16.row.col.f32.bf16.bf16.f32 "
        "{%0,%1,%2,%3}, {%4,%5,%6,%7}, {%8,%9}, {%0,%1,%2,%3};"
        : "+f"(c[0]), "+f"(c[1]), "+f"(c[2]), "+f"(c[3])
        : "r"(a[0]), "r"(a[1]), "r"(a[2]), "r"(a[3]), "r"(b[0]), "r"(b[1]));
}

// split a,b (fp32) -> packed bf16x2 hi + lo (a in low half, b in high half)
__device__ __forceinline__ void pack_hl(float a, float b, uint32_t& hi, uint32_t& lo) {
    __nv_bfloat16 h0 = __float2bfloat16(a);
    __nv_bfloat16 h1 = __float2bfloat16(b);
    __nv_bfloat16 l0 = __float2bfloat16(a - __bfloat162float(h0));
    __nv_bfloat16 l1 = __float2bfloat16(b - __bfloat162float(h1));
    __nv_bfloat162 ph; ph.x = h0; ph.y = h1;
    __nv_bfloat162 pl; pl.x = l0; pl.y = l1;
    hi = *(uint32_t*)&ph;
    lo = *(uint32_t*)&pl;
}

// ---------------------------------------------------------------------------
// Split-bf16 HMMA GEMM: C = A[M,K] @ W + bias (W transposed as B[N,K]).
// 3-term split, CTA 128x128, BK=32, 8 warps of 64x32, 3-stage cp.async.
// Output: fp32 (Cf != null) OR split bf16 hi/lo with optional 2^-3 scale on
// the first qcols columns (exact power of two -> commutes with the split).
// ---------------------------------------------------------------------------
#define PITCH 40                          // bf16 elems per GEMM smem row (32 + 8)
#define TILE_B (128 * PITCH * 2)          // 10240 bytes per tile
#define STAGE_B (4 * TILE_B)              // Ahi|Alo|Bhi|Blo = 40960
#define GEMM_SMEM (3 * STAGE_B)           // 122880

__global__ void __launch_bounds__(256, 1)
mma_gemm_kernel(const __nv_bfloat16* __restrict__ Ahi,
                const __nv_bfloat16* __restrict__ Alo,
                const __nv_bfloat16* __restrict__ Bhi,
                const __nv_bfloat16* __restrict__ Blo,
                const float* __restrict__ bias,
                float* __restrict__ Cf,
                __nv_bfloat16* __restrict__ Chi, __nv_bfloat16* __restrict__ Clo,
                int qcols, int M, int N, int K)
{
    extern __shared__ char smem[];
    const uint32_t sb = smem_u32(smem);
    const int tid = threadIdx.x;
    const int wid = tid >> 5;
    const int lid = tid & 31;
    const int bm = blockIdx.y * 128;
    const int bn = blockIdx.x * 128;
    const int m0 = (wid >> 2) * 64;
    const int n0 = (wid & 3) * 32;
    const int NCH = K / 32;

    float acc[4][4][4];
#pragma unroll
    for (int i = 0; i < 4; i++)
#pragma unroll
        for (int j = 0; j < 4; j++)
#pragma unroll
            for (int r = 0; r < 4; r++) acc[i][j][r] = 0.0f;

    auto cp_tile = [&](const __nv_bfloat16* g, int row0, int kc, uint32_t sdst) {
#pragma unroll
        for (int it = 0; it < 2; ++it) {
            int idx = tid + it * 256;
            int r = idx >> 2;
            int u = idx & 3;
            const __nv_bfloat16* src = g + (size_t)(row0 + r) * K + kc + u * 8;
            CP_ASYNC16(sdst + (r * PITCH + u * 8) * 2, src);
        }
    };
    auto load_stage = [&](int c, int stg) {
        uint32_t base = sb + stg * STAGE_B;
        int kc = c * 32;
        cp_tile(Ahi, bm, kc, base);
        cp_tile(Alo, bm, kc, base + TILE_B);
        cp_tile(Bhi, bn, kc, base + 2 * TILE_B);
        cp_tile(Blo, bn, kc, base + 3 * TILE_B);
    };

    load_stage(0, 0);
    CP_COMMIT();
    if (NCH > 1) { load_stage(1, 1); CP_COMMIT(); }

    const int a_row = lid & 15;
    const int a_k   = lid >> 4;
    const int b_row = lid & 7;
    const int b_k   = (lid >> 3) & 1;

    for (int c = 0; c < NCH; ++c) {
        if (c + 2 < NCH) {
            load_stage(c + 2, (c + 2) % 3);
            CP_COMMIT();
            CP_WAIT(2);
        } else {
            CP_WAIT(0);
        }
        __syncthreads();

        const uint32_t base = sb + (c % 3) * STAGE_B;
        const uint32_t pa_hi = base + ((m0 + a_row) * PITCH + a_k * 8) * 2;
        const uint32_t pa_lo = pa_hi + TILE_B;
        const uint32_t pb_hi = base + 2 * TILE_B + ((n0 + b_row) * PITCH + b_k * 8) * 2;
        const uint32_t pb_lo = pb_hi + TILE_B;

#pragma unroll
        for (int ks = 0; ks < 2; ++ks) {
            const uint32_t ko = ks * 32;
            uint32_t Ah[4][4], Al[4][4], Bh[4][2], Bl[4][2];
#pragma unroll
            for (int mf = 0; mf < 4; ++mf) {
                uint32_t off = ko + mf * (16 * PITCH * 2);
                LDSM_X4(Ah[mf][0], Ah[mf][1], Ah[mf][2], Ah[mf][3], pa_hi + off);
                LDSM_X4(Al[mf][0], Al[mf][1], Al[mf][2], Al[mf][3], pa_lo + off);
            }
#pragma unroll
            for (int nf = 0; nf < 4; ++nf) {
                uint32_t off = ko + nf * (8 * PITCH * 2);
                LDSM_X2(Bh[nf][0], Bh[nf][1], pb_hi + off);
                LDSM_X2(Bl[nf][0], Bl[nf][1], pb_lo + off);
            }
#pragma unroll
            for (int mf = 0; mf < 4; ++mf)
#pragma unroll
                for (int nf = 0; nf < 4; ++nf) {
                    mma_bf16(acc[mf][nf], Ah[mf], Bh[nf]);
                    mma_bf16(acc[mf][nf], Ah[mf], Bl[nf]);
                    mma_bf16(acc[mf][nf], Al[mf], Bh[nf]);
                }
        }
        __syncthreads();
    }

    // Epilogue
    const int grow = lid >> 2;
    const int gcol = (lid & 3) * 2;
#pragma unroll
    for (int mf = 0; mf < 4; ++mf) {
#pragma unroll
        for (int nf = 0; nf < 4; ++nf) {
            int r0  = bm + m0 + mf * 16 + grow;
            int col = bn + n0 + nf * 8 + gcol;
            float b0 = bias[col], b1 = bias[col + 1];
            float v0 = acc[mf][nf][0] + b0, v1 = acc[mf][nf][1] + b1;
            float v2 = acc[mf][nf][2] + b0, v3 = acc[mf][nf][3] + b1;
            if (Cf) {
                *(float2*)&Cf[(size_t)r0 * N + col]       = make_float2(v0, v1);
                *(float2*)&Cf[(size_t)(r0 + 8) * N + col] = make_float2(v2, v3);
            } else {
                if (col < qcols) { v0 *= 0.125f; v1 *= 0.125f; v2 *= 0.125f; v3 *= 0.125f; }
                uint32_t h01, l01, h23, l23;
                pack_hl(v0, v1, h01, l01);
                pack_hl(v2, v3, h23, l23);
                *(uint32_t*)&Chi[(size_t)r0 * N + col]       = h01;
                *(uint32_t*)&Clo[(size_t)r0 * N + col]       = l01;
                *(uint32_t*)&Chi[(size_t)(r0 + 8) * N + col] = h23;
                *(uint32_t*)&Clo[(size_t)(r0 + 8) * N + col] = l23;
            }
        }
    }
}

// ---------------------------------------------------------------------------
// fp32 -> (bf16 hi, bf16 lo) split, vectorized
// ---------------------------------------------------------------------------
__global__ void __launch_bounds__(256)
split_kernel(const float* __restrict__ in, __nv_bfloat16* __restrict__ hi,
             __nv_bfloat16* __restrict__ lo, int n4)
{
    int i = blockIdx.x * blockDim.x + threadIdx.x;
    if (i >= n4) return;
    float4 v = ((const float4*)in)[i];
    uint32_t h01, l01, h23, l23;
    pack_hl(v.x, v.y, h01, l01);
    pack_hl(v.z, v.w, h23, l23);
    ((uint32_t*)hi)[2 * i]     = h01;
    ((uint32_t*)hi)[2 * i + 1] = h23;
    ((uint32_t*)lo)[2 * i]     = l01;
    ((uint32_t*)lo)[2 * i + 1] = l23;
}

// ---------------------------------------------------------------------------
// W[K][N] fp32 -> T[N][K] bf16 hi/lo (tiled transpose)
// ---------------------------------------------------------------------------
__global__ void __launch_bounds__(256)
transpose_split_kernel(const float* __restrict__ W, __nv_bfloat16* __restrict__ Thi,
                       __nv_bfloat16* __restrict__ Tlo, int K, int N)
{
    __shared__ float t[32][33];
    const int n0 = blockIdx.x * 32;
    const int k0 = blockIdx.y * 32;
    const int tx = threadIdx.x, ty = threadIdx.y;
#pragma unroll
    for (int j = 0; j < 4; ++j)
        t[ty + j * 8][tx] = W[(size_t)(k0 + ty + j * 8) * N + n0 + tx];
    __syncthreads();
#pragma unroll
    for (int j = 0; j < 4; ++j) {
        int n = n0 + ty + j * 8;
        int k = k0 + tx;
        float v = t[tx][ty + j * 8];
        __nv_bfloat16 h = __float2bfloat16(v);
        Thi[(size_t)n * K + k] = h;
        Tlo[(size_t)n * K + k] = __float2bfloat16(v - __bfloat162float(h));
    }
}

// ---------------------------------------------------------------------------
// HMMA causal flash attention, split-bf16 for S=QK^T and P.V.
// q-tile 128 (8 warps x 16 rows), k-tile 64, Q pre-scaled by 2^-3 upstream.
// Attention tiles are 64 elems wide -> dedicated pitch APITCH = 72.
// (row stride 144 B == 16 B mod 128 -> 8 consecutive ldmatrix rows hit 8
//  distinct 16-byte banks: conflict-free.)
// ---------------------------------------------------------------------------
#define APITCH 72
#define AT_QTILE_B (128 * APITCH * 2)    // 18432
#define AT_KTILE_B (64 * APITCH * 2)     // 9216
#define AT_STAGE_B (4 * AT_KTILE_B)      // 36864
#define AT_SMEM (2 * AT_QTILE_B + 2 * AT_STAGE_B)   // 110592

__global__ void __launch_bounds__(256, 1)
attn_mma_kernel(const __nv_bfloat16* __restrict__ qvh,
                const __nv_bfloat16* __restrict__ qvl,
                __nv_bfloat16* __restrict__ yhi, __nv_bfloat16* __restrict__ ylo)
{
    extern __shared__ char smem[];
    const uint32_t sb = smem_u32(smem);
    const int tid = threadIdx.x, wid = tid >> 5, lid = tid & 31;
    const int qt = gridDim.x - 1 - blockIdx.x;   // heavy tiles launch first
    const int bh = blockIdx.y, b = bh / HH, h = bh % HH;
    const int q0 = qt * 128;
    const uint32_t sQh = sb, sQl = sb + AT_QTILE_B;
    const uint32_t sStage = sb + 2 * AT_QTILE_B;
    const size_t rowbase = (size_t)b * TT * N_QKV + h * DD;

    // Q tile load (hi/lo), 128 rows x 64 elems
#pragma unroll
    for (int it = 0; it < 4; ++it) {
        int idx = tid + it * 256;          // 0..1023
        int r = idx >> 3, u = idx & 7;
        size_t goff = rowbase + (size_t)(q0 + r) * N_QKV + u * 8;
        uint32_t d = (r * APITCH + u * 8) * 2;
        CP_ASYNC16(sQh + d, qvh + goff);
        CP_ASYNC16(sQl + d, qvl + goff);
    }

    auto load_kv = [&](int kt) {
        uint32_t base = sStage + (kt & 1) * AT_STAGE_B;
        int k0 = kt * 64;
#pragma unroll
        for (int it = 0; it < 8; ++it) {
            int idx = tid + it * 256;      // 0..2047
            int tile = idx >> 9, rem = idx & 511;
            int r = rem >> 3, u = rem & 7;
            const __nv_bfloat16* sp = (tile & 1) ? qvl : qvh;
            int coff = (tile < 2) ? CC : 2 * CC;
            const __nv_bfloat16* src = sp + rowbase + (size_t)(k0 + r) * N_QKV + coff + u * 8;
            CP_ASYNC16(base + tile * AT_KTILE_B + (r * APITCH + u * 8) * 2, src);
        }
    };

    const int nkt = 2 * qt + 2;
    load_kv(0);
    CP_COMMIT();
    load_kv(1);
    CP_COMMIT();
    CP_WAIT(1);
    __syncthreads();

    // hoist Q fragments (loop-invariant)
    uint32_t qfh[4][4], qfl[4][4];
    {
        const int a_row = lid & 15, a_k = lid >> 4;
        uint32_t ah = sQh + ((wid * 16 + a_row) * APITCH + a_k * 8) * 2;
        uint32_t al = sQl + ((wid * 16 + a_row) * APITCH + a_k * 8) * 2;
#pragma unroll
        for (int ks = 0; ks < 4; ++ks) {
            LDSM_X4(qfh[ks][0], qfh[ks][1], qfh[ks][2], qfh[ks][3], ah + ks * 32);
            LDSM_X4(qfl[ks][0], qfl[ks][1], qfl[ks][2], qfl[ks][3], al + ks * 32);
        }
    }

    float oacc[8][4];
#pragma unroll
    for (int nf = 0; nf < 8; ++nf)
#pragma unroll
        for (int r = 0; r < 4; ++r) oacc[nf][r] = 0.0f;
    float mrow0 = -1e30f, mrow1 = -1e30f, lrow0 = 0.0f, lrow1 = 0.0f;

    const int b_row = lid & 7, b_k = (lid >> 3) & 1;
    const int v_row = lid & 15;
    const int rloc  = lid >> 2;

    for (int kt = 0; kt < nkt; ++kt) {
        if (kt > 0) {
            if (kt + 1 < nkt) CP_WAIT(1); else CP_WAIT(0);
            __syncthreads();
        }
        const int k0 = kt * 64;
        const uint32_t stg = sStage + (kt & 1) * AT_STAGE_B;

        if (k0 <= q0 + wid * 16 + 15) {      // warp-uniform causal skip
            // ---- S = Q K^T (3-term split) ----
            float sa[8][4];
#pragma unroll
            for (int nf = 0; nf < 8; ++nf)
#pragma unroll
                for (int r = 0; r < 4; ++r) sa[nf][r] = 0.0f;

            const uint32_t kh_base = stg + (b_row * APITCH + b_k * 8) * 2;
            const uint32_t kl_base = kh_base + AT_KTILE_B;
#pragma unroll
            for (int nf = 0; nf < 8; ++nf) {
                uint32_t oh = kh_base + nf * (8 * APITCH * 2);
                uint32_t ol = kl_base + nf * (8 * APITCH * 2);
#pragma unroll
                for (int ks = 0; ks < 4; ++ks) {
                    uint32_t Bh[2], Bl[2];
                    LDSM_X2(Bh[0], Bh[1], oh + ks * 32);
                    LDSM_X2(Bl[0], Bl[1], ol + ks * 32);
                    mma_bf16(sa[nf], qfh[ks], Bh);
                    mma_bf16(sa[nf], qfh[ks], Bl);
                    mma_bf16(sa[nf], qfl[ks], Bh);
                }
            }

            const int rg0 = q0 + wid * 16 + rloc;
            const int rg1 = rg0 + 8;
            if (k0 + 63 > q0 + wid * 16) {   // diagonal tile: mask
#pragma unroll
                for (int nf = 0; nf < 8; ++nf) {
                    int c0 = k0 + nf * 8 + 2 * (lid & 3);
                    if (c0     > rg0) sa[nf][0] = -1e30f;
                    if (c0 + 1 > rg0) sa[nf][1] = -1e30f;
                    if (c0     > rg1) sa[nf][2] = -1e30f;
                    if (c0 + 1 > rg1) sa[nf][3] = -1e30f;
                }
            }

            // ---- online softmax (rows rloc, rloc+8; quad = lanes lid^1, lid^2) ----
            float mx0 = -1e30f, mx1 = -1e30f;
#pragma unroll
            for (int nf = 0; nf < 8; ++nf) {
                mx0 = fmaxf(mx0, fmaxf(sa[nf][0], sa[nf][1]));
                mx1 = fmaxf(mx1, fmaxf(sa[nf][2], sa[nf][3]));
            }
            mx0 = fmaxf(mx0, __shfl_xor_sync(0xffffffffu, mx0, 1));
            mx0 = fmaxf(mx0, __shfl_xor_sync(0xffffffffu, mx0, 2));
            mx1 = fmaxf(mx1, __shfl_xor_sync(0xffffffffu, mx1, 1));
            mx1 = fmaxf(mx1, __shfl_xor_sync(0xffffffffu, mx1, 2));
            float mn0 = fmaxf(mrow0, mx0), mn1 = fmaxf(mrow1, mx1);
            float corr0 = __expf(mrow0 - mn0), corr1 = __expf(mrow1 - mn1);
            float sum0 = 0.0f, sum1 = 0.0f;
#pragma unroll
            for (int nf = 0; nf < 8; ++nf) {
                sa[nf][0] = __expf(sa[nf][0] - mn0);
                sa[nf][1] = __expf(sa[nf][1] - mn0);
                sa[nf][2] = __expf(sa[nf][2] - mn1);
                sa[nf][3] = __expf(sa[nf][3] - mn1);
                sum0 += sa[nf][0] + sa[nf][1];
                sum1 += sa[nf][2] + sa[nf][3];
            }
            sum0 += __shfl_xor_sync(0xffffffffu, sum0, 1);
            sum0 += __shfl_xor_sync(0xffffffffu, sum0, 2);
            sum1 += __shfl_xor_sync(0xffffffffu, sum1, 1);
            sum1 += __shfl_xor_sync(0xffffffffu, sum1, 2);
            lrow0 = lrow0 * corr0 + sum0;
            lrow1 = lrow1 * corr1 + sum1;
            mrow0 = mn0; mrow1 = mn1;
#pragma unroll
            for (int nf = 0; nf < 8; ++nf) {
                oacc[nf][0] *= corr0; oacc[nf][1] *= corr0;
                oacc[nf][2] *= corr1; oacc[nf][3] *= corr1;
            }

            // ---- pack P c-frags -> A-frags (hi/lo) ----
            uint32_t pah[4][4], pal[4][4];
#pragma unroll
            for (int ks = 0; ks < 4; ++ks) {
                pack_hl(sa[2 * ks][0],     sa[2 * ks][1],     pah[ks][0], pal[ks][0]);
                pack_hl(sa[2 * ks][2],     sa[2 * ks][3],     pah[ks][1], pal[ks][1]);
                pack_hl(sa[2 * ks + 1][0], sa[2 * ks + 1][1], pah[ks][2], pal[ks][2]);
                pack_hl(sa[2 * ks + 1][2], sa[2 * ks + 1][3], pah[ks][3], pal[ks][3]);
            }

            // ---- O += P V (3-term split); V b-frags via ldmatrix.trans ----
            const uint32_t vh_base = stg + 2 * AT_KTILE_B + (v_row * APITCH) * 2;
            const uint32_t vl_base = vh_base + AT_KTILE_B;
#pragma unroll
            for (int nf = 0; nf < 8; ++nf) {
#pragma unroll
                for (int ks = 0; ks < 4; ++ks) {
                    uint32_t Bh[2], Bl[2];
                    uint32_t off = (ks * 16 * APITCH + nf * 8) * 2;
                    LDSM_X2_T(Bh[0], Bh[1], vh_base + off);
                    LDSM_X2_T(Bl[0], Bl[1], vl_base + off);
                    mma_bf16(oacc[nf], pah[ks], Bh);
                    mma_bf16(oacc[nf], pah[ks], Bl);
                    mma_bf16(oacc[nf], pal[ks], Bh);
                }
            }
        }
        __syncthreads();
        if (kt + 2 < nkt) { load_kv(kt + 2); CP_COMMIT(); }
    }

    // ---- epilogue: normalize and write y hi/lo ----
    const float inv0 = 1.0f / lrow0, inv1 = 1.0f / lrow1;
    const int rg0 = q0 + wid * 16 + rloc;
    const size_t y0 = ((size_t)(b * TT) + rg0) * CC + h * DD;
    const size_t y1 = y0 + 8 * CC;
#pragma unroll
    for (int nf = 0; nf < 8; ++nf) {
        int col = nf * 8 + 2 * (lid & 3);
        uint32_t h01, l01, h23, l23;
        pack_hl(oacc[nf][0] * inv0, oacc[nf][1] * inv0, h01, l01);
        pack_hl(oacc[nf][2] * inv1, oacc[nf][3] * inv1, h23, l23);
        *(uint32_t*)&yhi[y0 + col] = h01;
        *(uint32_t*)&ylo[y0 + col] = l01;
        *(uint32_t*)&yhi[y1 + col] = h23;
        *(uint32_t*)&ylo[y1 + col] = l23;
    }
}

// ---------------------------------------------------------------------------
// Launch
// ---------------------------------------------------------------------------
extern "C" void kernel_launch(void* const* d_in, const int* in_sizes, int n_in,
                              void* d_out, int out_size)
{
    const float* x     = (const float*)d_in[0];
    const float* wqkv  = (const float*)d_in[1];
    const float* bqkv  = (const float*)d_in[2];
    const float* wproj = (const float*)d_in[3];
    const float* bproj = (const float*)d_in[4];
    float* out = (float*)d_out;

    __nv_bfloat16 *qkh, *qkl, *xh, *xl, *wqh, *wql, *wph, *wpl, *yh, *yl;
    cudaGetSymbolAddress((void**)&qkh, g_qkv_hi);
    cudaGetSymbolAddress((void**)&qkl, g_qkv_lo);
    cudaGetSymbolAddress((void**)&xh,  g_x_hi);
    cudaGetSymbolAddress((void**)&xl,  g_x_lo);
    cudaGetSymbolAddress((void**)&wqh, g_wq_hi);
    cudaGetSymbolAddress((void**)&wql, g_wq_lo);
    cudaGetSymbolAddress((void**)&wph, g_wp_hi);
    cudaGetSymbolAddress((void**)&wpl, g_wp_lo);
    cudaGetSymbolAddress((void**)&yh,  g_y_hi);
    cudaGetSymbolAddress((void**)&yl,  g_y_lo);

    cudaFuncSetAttribute(mma_gemm_kernel,
                         cudaFuncAttributeMaxDynamicSharedMemorySize, GEMM_SMEM);
    cudaFuncSetAttribute(attn_mma_kernel,
                         cudaFuncAttributeMaxDynamicSharedMemorySize, AT_SMEM);

    // Prep: split x; transpose+split both weight matrices
    split_kernel<<<(M_ROWS * CC / 4 + 255) / 256, 256>>>(x, xh, xl, M_ROWS * CC / 4);
    transpose_split_kernel<<<dim3(N_QKV / 32, CC / 32), dim3(32, 8)>>>(wqkv, wqh, wql, CC, N_QKV);
    transpose_split_kernel<<<dim3(CC / 32, CC / 32), dim3(32, 8)>>>(wproj, wph, wpl, CC, CC);

    // 1) qkv = x @ Wqkv + b -> split bf16 hi/lo, q-columns pre-scaled by 2^-3
    mma_gemm_kernel<<<dim3(N_QKV / 128, M_ROWS / 128), 256, GEMM_SMEM>>>(
        xh, xl, wqh, wql, bqkv, nullptr, qkh, qkl, CC, M_ROWS, N_QKV, CC);

    // 2) HMMA causal flash attention -> y hi/lo
    attn_mma_kernel<<<dim3(TT / 128, BB * HH), 256, AT_SMEM>>>(qkh, qkl, yh, yl);

    // 3) out = y @ Wproj + b  (fp32 output)
    mma_gemm_kernel<<<dim3(CC / 128, M_ROWS / 128), 256, GEMM_SMEM>>>(
        yh, yl, wph, wpl, bproj, out, nullptr, nullptr, 0, M_ROWS, CC, CC);
}

// round 13
// speedup vs baseline: 2.5287x; 1.1002x over previous
#include <cuda_runtime.h>
#include <cuda_bf16.h>
#include <cstdint>
#include <math.h>

// Problem constants
#define BB 8
#define TT 1024
#define CC 768
#define HH 12
#define DD 64
#define M_ROWS (BB * TT)          // 8192
#define N_QKV  (3 * CC)           // 2304

// ---------------------------------------------------------------------------
// Scratch (device globals; runtime allocation is forbidden)
// ---------------------------------------------------------------------------
__device__ __nv_bfloat16 g_qkv_hi[M_ROWS * N_QKV];
__device__ __nv_bfloat16 g_qkv_lo[M_ROWS * N_QKV];
__device__ __nv_bfloat16 g_x_hi[M_ROWS * CC];
__device__ __nv_bfloat16 g_x_lo[M_ROWS * CC];
__device__ __nv_bfloat16 g_wq_hi[N_QKV * CC];      // Wqkv^T [2304][768]
__device__ __nv_bfloat16 g_wq_lo[N_QKV * CC];
__device__ __nv_bfloat16 g_wp_hi[CC * CC];         // Wproj^T [768][768]
__device__ __nv_bfloat16 g_wp_lo[CC * CC];
__device__ __nv_bfloat16 g_y_hi[M_ROWS * CC];      // attention out split
__device__ __nv_bfloat16 g_y_lo[M_ROWS * CC];

// ---------------------------------------------------------------------------
// Portable tensor-core helpers: mma.sync + ldmatrix + cp.async
// ---------------------------------------------------------------------------
__device__ __forceinline__ uint32_t smem_u32(const void* p) {
    uint32_t a;
    asm("{ .reg .u64 t; cvta.to.shared.u64 t, %1; cvt.u32.u64 %0, t; }"
        : "=r"(a) : "l"(p));
    return a;
}

#define CP_ASYNC16(dst, src) \
    asm volatile("cp.async.cg.shared.global [%0], [%1], 16;" \
                 :: "r"(dst), "l"(src) : "memory")
#define CP_COMMIT() asm volatile("cp.async.commit_group;" ::: "memory")
#define CP_WAIT(n)  asm volatile("cp.async.wait_group %0;" :: "n"(n) : "memory")

#define LDSM_X4(r0, r1, r2, r3, addr) \
    asm volatile("ldmatrix.sync.aligned.m8n8.x4.shared.b16 {%0,%1,%2,%3}, [%4];" \
                 : "=r"(r0), "=r"(r1), "=r"(r2), "=r"(r3) : "r"(addr))
#define LDSM_X2(r0, r1, addr) \
    asm volatile("ldmatrix.sync.aligned.m8n8.x2.shared.b16 {%0,%1}, [%2];" \
                 : "=r"(r0), "=r"(r1) : "r"(addr))
#define LDSM_X2_T(r0, r1, addr) \
    asm volatile("ldmatrix.sync.aligned.m8n8.x2.trans.shared.b16 {%0,%1}, [%2];" \
                 : "=r"(r0), "=r"(r1) : "r"(addr))

__device__ __forceinline__ void mma_bf16(float* c, const uint32_t* a, const uint32_t* b) {
    asm volatile(
        "mma.sync.aligned.m16n8k16.row.col.f32.bf16.bf16.f32 "
        "{%0,%1,%2,%3}, {%4,%5,%6,%7}, {%8,%9}, {%0,%1,%2,%3};"
        : "+f"(c[0]), "+f"(c[1]), "+f"(c[2]), "+f"(c[3])
        : "r"(a[0]), "r"(a[1]), "r"(a[2]), "r"(a[3]), "r"(b[0]), "r"(b[1]));
}

// split a,b (fp32) -> packed bf16x2 hi + lo (a in low half, b in high half)
__device__ __forceinline__ void pack_hl(float a, float b, uint32_t& hi, uint32_t& lo) {
    __nv_bfloat16 h0 = __float2bfloat16(a);
    __nv_bfloat16 h1 = __float2bfloat16(b);
    __nv_bfloat16 l0 = __float2bfloat16(a - __bfloat162float(h0));
    __nv_bfloat16 l1 = __float2bfloat16(b - __bfloat162float(h1));
    __nv_bfloat162 ph; ph.x = h0; ph.y = h1;
    __nv_bfloat162 pl; pl.x = l0; pl.y = l1;
    hi = *(uint32_t*)&ph;
    lo = *(uint32_t*)&pl;
}

// ---------------------------------------------------------------------------
// Split-bf16 HMMA GEMM: C = A[M,K] @ W + bias (W transposed as B[N,K]).
// 3-term split, CTA 128x128, BK=32, 8 warps of 64x32, 2-stage cp.async,
// 2 CTAs/SM (regs capped at 128 via launch_bounds, B-frags hoisted per
// k-step, A-frags streamed one mf at a time).
// ---------------------------------------------------------------------------
#define PITCH 40                          // bf16 elems per GEMM smem row (32 + 8)
#define TILE_B (128 * PITCH * 2)          // 10240 bytes per tile
#define STAGE_B (4 * TILE_B)              // Ahi|Alo|Bhi|Blo = 40960
#define GEMM_SMEM (2 * STAGE_B)           // 81920

__global__ void __launch_bounds__(256, 2)
mma_gemm_kernel(const __nv_bfloat16* __restrict__ Ahi,
                const __nv_bfloat16* __restrict__ Alo,
                const __nv_bfloat16* __restrict__ Bhi,
                const __nv_bfloat16* __restrict__ Blo,
                const float* __restrict__ bias,
                float* __restrict__ Cf,
                __nv_bfloat16* __restrict__ Chi, __nv_bfloat16* __restrict__ Clo,
                int qcols, int M, int N, int K)
{
    extern __shared__ char smem[];
    const uint32_t sb = smem_u32(smem);
    const int tid = threadIdx.x;
    const int wid = tid >> 5;
    const int lid = tid & 31;
    const int bm = blockIdx.y * 128;
    const int bn = blockIdx.x * 128;
    const int m0 = (wid >> 2) * 64;
    const int n0 = (wid & 3) * 32;
    const int NCH = K / 32;

    float acc[4][4][4];
#pragma unroll
    for (int i = 0; i < 4; i++)
#pragma unroll
        for (int j = 0; j < 4; j++)
#pragma unroll
            for (int r = 0; r < 4; r++) acc[i][j][r] = 0.0f;

    auto cp_tile = [&](const __nv_bfloat16* g, int row0, int kc, uint32_t sdst) {
#pragma unroll
        for (int it = 0; it < 2; ++it) {
            int idx = tid + it * 256;
            int r = idx >> 2;
            int u = idx & 3;
            const __nv_bfloat16* src = g + (size_t)(row0 + r) * K + kc + u * 8;
            CP_ASYNC16(sdst + (r * PITCH + u * 8) * 2, src);
        }
    };
    auto load_stage = [&](int c, int stg) {
        uint32_t base = sb + stg * STAGE_B;
        int kc = c * 32;
        cp_tile(Ahi, bm, kc, base);
        cp_tile(Alo, bm, kc, base + TILE_B);
        cp_tile(Bhi, bn, kc, base + 2 * TILE_B);
        cp_tile(Blo, bn, kc, base + 3 * TILE_B);
    };

    load_stage(0, 0);
    CP_COMMIT();

    const int a_row = lid & 15;
    const int a_k   = lid >> 4;
    const int b_row = lid & 7;
    const int b_k   = (lid >> 3) & 1;

    for (int c = 0; c < NCH; ++c) {
        if (c + 1 < NCH) {
            load_stage(c + 1, (c + 1) & 1);
            CP_COMMIT();
            CP_WAIT(1);
        } else {
            CP_WAIT(0);
        }
        __syncthreads();

        const uint32_t base = sb + (c & 1) * STAGE_B;
        const uint32_t pa_hi = base + ((m0 + a_row) * PITCH + a_k * 8) * 2;
        const uint32_t pa_lo = pa_hi + TILE_B;
        const uint32_t pb_hi = base + 2 * TILE_B + ((n0 + b_row) * PITCH + b_k * 8) * 2;
        const uint32_t pb_lo = pb_hi + TILE_B;

#pragma unroll
        for (int ks = 0; ks < 2; ++ks) {
            const uint32_t ko = ks * 32;
            // hoist B fragments for this k-step (16 regs hi + 16 lo)
            uint32_t Bh[4][2], Bl[4][2];
#pragma unroll
            for (int nf = 0; nf < 4; ++nf) {
                uint32_t off = ko + nf * (8 * PITCH * 2);
                LDSM_X2(Bh[nf][0], Bh[nf][1], pb_hi + off);
                LDSM_X2(Bl[nf][0], Bl[nf][1], pb_lo + off);
            }
            // stream A fragments one mf at a time (8 live regs)
#pragma unroll
            for (int mf = 0; mf < 4; ++mf) {
                uint32_t Ah[4], Al[4];
                uint32_t off = ko + mf * (16 * PITCH * 2);
                LDSM_X4(Ah[0], Ah[1], Ah[2], Ah[3], pa_hi + off);
                LDSM_X4(Al[0], Al[1], Al[2], Al[3], pa_lo + off);
#pragma unroll
                for (int nf = 0; nf < 4; ++nf) {
                    mma_bf16(acc[mf][nf], Ah, Bh[nf]);
                    mma_bf16(acc[mf][nf], Ah, Bl[nf]);
                    mma_bf16(acc[mf][nf], Al, Bh[nf]);
                }
            }
        }
        __syncthreads();
    }

    // Epilogue
    const int grow = lid >> 2;
    const int gcol = (lid & 3) * 2;
#pragma unroll
    for (int mf = 0; mf < 4; ++mf) {
#pragma unroll
        for (int nf = 0; nf < 4; ++nf) {
            int r0  = bm + m0 + mf * 16 + grow;
            int col = bn + n0 + nf * 8 + gcol;
            float b0 = bias[col], b1 = bias[col + 1];
            float v0 = acc[mf][nf][0] + b0, v1 = acc[mf][nf][1] + b1;
            float v2 = acc[mf][nf][2] + b0, v3 = acc[mf][nf][3] + b1;
            if (Cf) {
                *(float2*)&Cf[(size_t)r0 * N + col]       = make_float2(v0, v1);
                *(float2*)&Cf[(size_t)(r0 + 8) * N + col] = make_float2(v2, v3);
            } else {
                if (col < qcols) { v0 *= 0.125f; v1 *= 0.125f; v2 *= 0.125f; v3 *= 0.125f; }
                uint32_t h01, l01, h23, l23;
                pack_hl(v0, v1, h01, l01);
                pack_hl(v2, v3, h23, l23);
                *(uint32_t*)&Chi[(size_t)r0 * N + col]       = h01;
                *(uint32_t*)&Clo[(size_t)r0 * N + col]       = l01;
                *(uint32_t*)&Chi[(size_t)(r0 + 8) * N + col] = h23;
                *(uint32_t*)&Clo[(size_t)(r0 + 8) * N + col] = l23;
            }
        }
    }
}

// ---------------------------------------------------------------------------
// fp32 -> (bf16 hi, bf16 lo) split, vectorized
// ---------------------------------------------------------------------------
__global__ void __launch_bounds__(256)
split_kernel(const float* __restrict__ in, __nv_bfloat16* __restrict__ hi,
             __nv_bfloat16* __restrict__ lo, int n4)
{
    int i = blockIdx.x * blockDim.x + threadIdx.x;
    if (i >= n4) return;
    float4 v = ((const float4*)in)[i];
    uint32_t h01, l01, h23, l23;
    pack_hl(v.x, v.y, h01, l01);
    pack_hl(v.z, v.w, h23, l23);
    ((uint32_t*)hi)[2 * i]     = h01;
    ((uint32_t*)hi)[2 * i + 1] = h23;
    ((uint32_t*)lo)[2 * i]     = l01;
    ((uint32_t*)lo)[2 * i + 1] = l23;
}

// ---------------------------------------------------------------------------
// W[K][N] fp32 -> T[N][K] bf16 hi/lo (tiled transpose)
// ---------------------------------------------------------------------------
__global__ void __launch_bounds__(256)
transpose_split_kernel(const float* __restrict__ W, __nv_bfloat16* __restrict__ Thi,
                       __nv_bfloat16* __restrict__ Tlo, int K, int N)
{
    __shared__ float t[32][33];
    const int n0 = blockIdx.x * 32;
    const int k0 = blockIdx.y * 32;
    const int tx = threadIdx.x, ty = threadIdx.y;
#pragma unroll
    for (int j = 0; j < 4; ++j)
        t[ty + j * 8][tx] = W[(size_t)(k0 + ty + j * 8) * N + n0 + tx];
    __syncthreads();
#pragma unroll
    for (int j = 0; j < 4; ++j) {
        int n = n0 + ty + j * 8;
        int k = k0 + tx;
        float v = t[tx][ty + j * 8];
        __nv_bfloat16 h = __float2bfloat16(v);
        Thi[(size_t)n * K + k] = h;
        Tlo[(size_t)n * K + k] = __float2bfloat16(v - __bfloat162float(h));
    }
}

// ---------------------------------------------------------------------------
// HMMA causal flash attention, split-bf16 for S=QK^T and P.V.
// q-tile 128 (8 warps x 16 rows), k-tile 64, Q pre-scaled by 2^-3 upstream.
// APITCH = 72 (row stride 144 B == 16 B mod 128 -> conflict-free ldmatrix).
// ---------------------------------------------------------------------------
#define APITCH 72
#define AT_QTILE_B (128 * APITCH * 2)    // 18432
#define AT_KTILE_B (64 * APITCH * 2)     // 9216
#define AT_STAGE_B (4 * AT_KTILE_B)      // 36864
#define AT_SMEM (2 * AT_QTILE_B + 2 * AT_STAGE_B)   // 110592

__global__ void __launch_bounds__(256, 1)
attn_mma_kernel(const __nv_bfloat16* __restrict__ qvh,
                const __nv_bfloat16* __restrict__ qvl,
                __nv_bfloat16* __restrict__ yhi, __nv_bfloat16* __restrict__ ylo)
{
    extern __shared__ char smem[];
    const uint32_t sb = smem_u32(smem);
    const int tid = threadIdx.x, wid = tid >> 5, lid = tid & 31;
    const int qt = gridDim.x - 1 - blockIdx.x;   // heavy tiles launch first
    const int bh = blockIdx.y, b = bh / HH, h = bh % HH;
    const int q0 = qt * 128;
    const uint32_t sQh = sb, sQl = sb + AT_QTILE_B;
    const uint32_t sStage = sb + 2 * AT_QTILE_B;
    const size_t rowbase = (size_t)b * TT * N_QKV + h * DD;

    // Q tile load (hi/lo), 128 rows x 64 elems
#pragma unroll
    for (int it = 0; it < 4; ++it) {
        int idx = tid + it * 256;          // 0..1023
        int r = idx >> 3, u = idx & 7;
        size_t goff = rowbase + (size_t)(q0 + r) * N_QKV + u * 8;
        uint32_t d = (r * APITCH + u * 8) * 2;
        CP_ASYNC16(sQh + d, qvh + goff);
        CP_ASYNC16(sQl + d, qvl + goff);
    }

    auto load_kv = [&](int kt) {
        uint32_t base = sStage + (kt & 1) * AT_STAGE_B;
        int k0 = kt * 64;
#pragma unroll
        for (int it = 0; it < 8; ++it) {
            int idx = tid + it * 256;      // 0..2047
            int tile = idx >> 9, rem = idx & 511;
            int r = rem >> 3, u = rem & 7;
            const __nv_bfloat16* sp = (tile & 1) ? qvl : qvh;
            int coff = (tile < 2) ? CC : 2 * CC;
            const __nv_bfloat16* src = sp + rowbase + (size_t)(k0 + r) * N_QKV + coff + u * 8;
            CP_ASYNC16(base + tile * AT_KTILE_B + (r * APITCH + u * 8) * 2, src);
        }
    };

    const int nkt = 2 * qt + 2;
    load_kv(0);
    CP_COMMIT();
    load_kv(1);
    CP_COMMIT();
    CP_WAIT(1);
    __syncthreads();

    // hoist Q fragments (loop-invariant)
    uint32_t qfh[4][4], qfl[4][4];
    {
        const int a_row = lid & 15, a_k = lid >> 4;
        uint32_t ah = sQh + ((wid * 16 + a_row) * APITCH + a_k * 8) * 2;
        uint32_t al = sQl + ((wid * 16 + a_row) * APITCH + a_k * 8) * 2;
#pragma unroll
        for (int ks = 0; ks < 4; ++ks) {
            LDSM_X4(qfh[ks][0], qfh[ks][1], qfh[ks][2], qfh[ks][3], ah + ks * 32);
            LDSM_X4(qfl[ks][0], qfl[ks][1], qfl[ks][2], qfl[ks][3], al + ks * 32);
        }
    }

    float oacc[8][4];
#pragma unroll
    for (int nf = 0; nf < 8; ++nf)
#pragma unroll
        for (int r = 0; r < 4; ++r) oacc[nf][r] = 0.0f;
    float mrow0 = -1e30f, mrow1 = -1e30f, lrow0 = 0.0f, lrow1 = 0.0f;

    const int b_row = lid & 7, b_k = (lid >> 3) & 1;
    const int v_row = lid & 15;
    const int rloc  = lid >> 2;

    for (int kt = 0; kt < nkt; ++kt) {
        if (kt > 0) {
            if (kt + 1 < nkt) CP_WAIT(1); else CP_WAIT(0);
            __syncthreads();
        }
        const int k0 = kt * 64;
        const uint32_t stg = sStage + (kt & 1) * AT_STAGE_B;

        if (k0 <= q0 + wid * 16 + 15) {      // warp-uniform causal skip
            // ---- S = Q K^T (3-term split) ----
            float sa[8][4];
#pragma unroll
            for (int nf = 0; nf < 8; ++nf)
#pragma unroll
                for (int r = 0; r < 4; ++r) sa[nf][r] = 0.0f;

            const uint32_t kh_base = stg + (b_row * APITCH + b_k * 8) * 2;
            const uint32_t kl_base = kh_base + AT_KTILE_B;
#pragma unroll
            for (int nf = 0; nf < 8; ++nf) {
                uint32_t oh = kh_base + nf * (8 * APITCH * 2);
                uint32_t ol = kl_base + nf * (8 * APITCH * 2);
#pragma unroll
                for (int ks = 0; ks < 4; ++ks) {
                    uint32_t Bh[2], Bl[2];
                    LDSM_X2(Bh[0], Bh[1], oh + ks * 32);
                    LDSM_X2(Bl[0], Bl[1], ol + ks * 32);
                    mma_bf16(sa[nf], qfh[ks], Bh);
                    mma_bf16(sa[nf], qfh[ks], Bl);
                    mma_bf16(sa[nf], qfl[ks], Bh);
                }
            }

            const int rg0 = q0 + wid * 16 + rloc;
            const int rg1 = rg0 + 8;
            if (k0 + 63 > q0 + wid * 16) {   // diagonal tile: mask
#pragma unroll
                for (int nf = 0; nf < 8; ++nf) {
                    int c0 = k0 + nf * 8 + 2 * (lid & 3);
                    if (c0     > rg0) sa[nf][0] = -1e30f;
                    if (c0 + 1 > rg0) sa[nf][1] = -1e30f;
                    if (c0     > rg1) sa[nf][2] = -1e30f;
                    if (c0 + 1 > rg1) sa[nf][3] = -1e30f;
                }
            }

            // ---- online softmax (rows rloc, rloc+8; quad reduce) ----
            float mx0 = -1e30f, mx1 = -1e30f;
#pragma unroll
            for (int nf = 0; nf < 8; ++nf) {
                mx0 = fmaxf(mx0, fmaxf(sa[nf][0], sa[nf][1]));
                mx1 = fmaxf(mx1, fmaxf(sa[nf][2], sa[nf][3]));
            }
            mx0 = fmaxf(mx0, __shfl_xor_sync(0xffffffffu, mx0, 1));
            mx0 = fmaxf(mx0, __shfl_xor_sync(0xffffffffu, mx0, 2));
            mx1 = fmaxf(mx1, __shfl_xor_sync(0xffffffffu, mx1, 1));
            mx1 = fmaxf(mx1, __shfl_xor_sync(0xffffffffu, mx1, 2));
            float mn0 = fmaxf(mrow0, mx0), mn1 = fmaxf(mrow1, mx1);
            float corr0 = __expf(mrow0 - mn0), corr1 = __expf(mrow1 - mn1);
            float sum0 = 0.0f, sum1 = 0.0f;
#pragma unroll
            for (int nf = 0; nf < 8; ++nf) {
                sa[nf][0] = __expf(sa[nf][0] - mn0);
                sa[nf][1] = __expf(sa[nf][1] - mn0);
                sa[nf][2] = __expf(sa[nf][2] - mn1);
                sa[nf][3] = __expf(sa[nf][3] - mn1);
                sum0 += sa[nf][0] + sa[nf][1];
                sum1 += sa[nf][2] + sa[nf][3];
            }
            sum0 += __shfl_xor_sync(0xffffffffu, sum0, 1);
            sum0 += __shfl_xor_sync(0xffffffffu, sum0, 2);
            sum1 += __shfl_xor_sync(0xffffffffu, sum1, 1);
            sum1 += __shfl_xor_sync(0xffffffffu, sum1, 2);
            lrow0 = lrow0 * corr0 + sum0;
            lrow1 = lrow1 * corr1 + sum1;
            mrow0 = mn0; mrow1 = mn1;
#pragma unroll
            for (int nf = 0; nf < 8; ++nf) {
                oacc[nf][0] *= corr0; oacc[nf][1] *= corr0;
                oacc[nf][2] *= corr1; oacc[nf][3] *= corr1;
            }

            // ---- pack P c-frags -> A-frags (hi/lo) ----
            uint32_t pah[4][4], pal[4][4];
#pragma unroll
            for (int ks = 0; ks < 4; ++ks) {
                pack_hl(sa[2 * ks][0],     sa[2 * ks][1],     pah[ks][0], pal[ks][0]);
                pack_hl(sa[2 * ks][2],     sa[2 * ks][3],     pah[ks][1], pal[ks][1]);
                pack_hl(sa[2 * ks + 1][0], sa[2 * ks + 1][1], pah[ks][2], pal[ks][2]);
                pack_hl(sa[2 * ks + 1][2], sa[2 * ks + 1][3], pah[ks][3], pal[ks][3]);
            }

            // ---- O += P V (3-term split); V b-frags via ldmatrix.trans ----
            const uint32_t vh_base = stg + 2 * AT_KTILE_B + (v_row * APITCH) * 2;
            const uint32_t vl_base = vh_base + AT_KTILE_B;
#pragma unroll
            for (int nf = 0; nf < 8; ++nf) {
#pragma unroll
                for (int ks = 0; ks < 4; ++ks) {
                    uint32_t Bh[2], Bl[2];
                    uint32_t off = (ks * 16 * APITCH + nf * 8) * 2;
                    LDSM_X2_T(Bh[0], Bh[1], vh_base + off);
                    LDSM_X2_T(Bl[0], Bl[1], vl_base + off);
                    mma_bf16(oacc[nf], pah[ks], Bh);
                    mma_bf16(oacc[nf], pah[ks], Bl);
                    mma_bf16(oacc[nf], pal[ks], Bh);
                }
            }
        }
        __syncthreads();
        if (kt + 2 < nkt) { load_kv(kt + 2); CP_COMMIT(); }
    }

    // ---- epilogue: normalize and write y hi/lo ----
    const float inv0 = 1.0f / lrow0, inv1 = 1.0f / lrow1;
    const int rg0 = q0 + wid * 16 + rloc;
    const size_t y0 = ((size_t)(b * TT) + rg0) * CC + h * DD;
    const size_t y1 = y0 + 8 * CC;
#pragma unroll
    for (int nf = 0; nf < 8; ++nf) {
        int col = nf * 8 + 2 * (lid & 3);
        uint32_t h01, l01, h23, l23;
        pack_hl(oacc[nf][0] * inv0, oacc[nf][1] * inv0, h01, l01);
        pack_hl(oacc[nf][2] * inv1, oacc[nf][3] * inv1, h23, l23);
        *(uint32_t*)&yhi[y0 + col] = h01;
        *(uint32_t*)&ylo[y0 + col] = l01;
        *(uint32_t*)&yhi[y1 + col] = h23;
        *(uint32_t*)&ylo[y1 + col] = l23;
    }
}

// ---------------------------------------------------------------------------
// Launch
// ---------------------------------------------------------------------------
extern "C" void kernel_launch(void* const* d_in, const int* in_sizes, int n_in,
                              void* d_out, int out_size)
{
    const float* x     = (const float*)d_in[0];
    const float* wqkv  = (const float*)d_in[1];
    const float* bqkv  = (const float*)d_in[2];
    const float* wproj = (const float*)d_in[3];
    const float* bproj = (const float*)d_in[4];
    float* out = (float*)d_out;

    __nv_bfloat16 *qkh, *qkl, *xh, *xl, *wqh, *wql, *wph, *wpl, *yh, *yl;
    cudaGetSymbolAddress((void**)&qkh, g_qkv_hi);
    cudaGetSymbolAddress((void**)&qkl, g_qkv_lo);
    cudaGetSymbolAddress((void**)&xh,  g_x_hi);
    cudaGetSymbolAddress((void**)&xl,  g_x_lo);
    cudaGetSymbolAddress((void**)&wqh, g_wq_hi);
    cudaGetSymbolAddress((void**)&wql, g_wq_lo);
    cudaGetSymbolAddress((void**)&wph, g_wp_hi);
    cudaGetSymbolAddress((void**)&wpl, g_wp_lo);
    cudaGetSymbolAddress((void**)&yh,  g_y_hi);
    cudaGetSymbolAddress((void**)&yl,  g_y_lo);

    cudaFuncSetAttribute(mma_gemm_kernel,
                         cudaFuncAttributeMaxDynamicSharedMemorySize, GEMM_SMEM);
    cudaFuncSetAttribute(attn_mma_kernel,
                         cudaFuncAttributeMaxDynamicSharedMemorySize, AT_SMEM);

    // Prep: split x; transpose+split both weight matrices
    split_kernel<<<(M_ROWS * CC / 4 + 255) / 256, 256>>>(x, xh, xl, M_ROWS * CC / 4);
    transpose_split_kernel<<<dim3(N_QKV / 32, CC / 32), dim3(32, 8)>>>(wqkv, wqh, wql, CC, N_QKV);
    transpose_split_kernel<<<dim3(CC / 32, CC / 32), dim3(32, 8)>>>(wproj, wph, wpl, CC, CC);

    // 1) qkv = x @ Wqkv + b -> split bf16 hi/lo, q-columns pre-scaled by 2^-3
    mma_gemm_kernel<<<dim3(N_QKV / 128, M_ROWS / 128), 256, GEMM_SMEM>>>(
        xh, xl, wqh, wql, bqkv, nullptr, qkh, qkl, CC, M_ROWS, N_QKV, CC);

    // 2) HMMA causal flash attention -> y hi/lo
    attn_mma_kernel<<<dim3(TT / 128, BB * HH), 256, AT_SMEM>>>(qkh, qkl, yh, yl);

    // 3) out = y @ Wproj + b  (fp32 output)
    mma_gemm_kernel<<<dim3(CC / 128, M_ROWS / 128), 256, GEMM_SMEM>>>(
        yh, yl, wph, wpl, bproj, out, nullptr, nullptr, 0, M_ROWS, CC, CC);
}

// round 14
// speedup vs baseline: 3.0892x; 1.2217x over previous
#include <cuda_runtime.h>
#include <cuda_bf16.h>
#include <cuda_fp16.h>
#include <cstdint>
#include <math.h>

// Problem constants
#define BB 8
#define TT 1024
#define CC 768
#define HH 12
#define DD 64
#define M_ROWS (BB * TT)          // 8192
#define N_QKV  (3 * CC)           // 2304

// ---------------------------------------------------------------------------
// Scratch (device globals; runtime allocation is forbidden)
// ---------------------------------------------------------------------------
__device__ __nv_bfloat16 g_qkv_hi[M_ROWS * N_QKV];   // GEMM1 out (attention in)
__device__ __nv_bfloat16 g_qkv_lo[M_ROWS * N_QKV];
__device__ __half g_x_hi[M_ROWS * CC];               // x split (fp16)
__device__ __half g_x_lo[M_ROWS * CC];
__device__ __half g_wq_hi[N_QKV * CC];               // Wqkv^T fp16 (hi only)
__device__ __half g_wp_hi[CC * CC];                  // Wproj^T fp16 (hi only)
__device__ __half g_y_hi[M_ROWS * CC];               // attention out (fp16 split)
__device__ __half g_y_lo[M_ROWS * CC];

// ---------------------------------------------------------------------------
// Portable tensor-core helpers: mma.sync + ldmatrix + cp.async
// ---------------------------------------------------------------------------
__device__ __forceinline__ uint32_t smem_u32(const void* p) {
    uint32_t a;
    asm("{ .reg .u64 t; cvta.to.shared.u64 t, %1; cvt.u32.u64 %0, t; }"
        : "=r"(a) : "l"(p));
    return a;
}

#define CP_ASYNC16(dst, src) \
    asm volatile("cp.async.cg.shared.global [%0], [%1], 16;" \
                 :: "r"(dst), "l"(src) : "memory")
#define CP_COMMIT() asm volatile("cp.async.commit_group;" ::: "memory")
#define CP_WAIT(n)  asm volatile("cp.async.wait_group %0;" :: "n"(n) : "memory")

#define LDSM_X4(r0, r1, r2, r3, addr) \
    asm volatile("ldmatrix.sync.aligned.m8n8.x4.shared.b16 {%0,%1,%2,%3}, [%4];" \
                 : "=r"(r0), "=r"(r1), "=r"(r2), "=r"(r3) : "r"(addr))
#define LDSM_X2(r0, r1, addr) \
    asm volatile("ldmatrix.sync.aligned.m8n8.x2.shared.b16 {%0,%1}, [%2];" \
                 : "=r"(r0), "=r"(r1) : "r"(addr))
#define LDSM_X2_T(r0, r1, addr) \
    asm volatile("ldmatrix.sync.aligned.m8n8.x2.trans.shared.b16 {%0,%1}, [%2];" \
                 : "=r"(r0), "=r"(r1) : "r"(addr))

__device__ __forceinline__ void mma_bf16(float* c, const uint32_t* a, const uint32_t* b) {
    asm volatile(
        "mma.sync.aligned.m16n8k16.row.col.f32.bf16.bf16.f32 "
        "{%0,%1,%2,%3}, {%4,%5,%6,%7}, {%8,%9}, {%0,%1,%2,%3};"
        : "+f"(c[0]), "+f"(c[1]), "+f"(c[2]), "+f"(c[3])
        : "r"(a[0]), "r"(a[1]), "r"(a[2]), "r"(a[3]), "r"(b[0]), "r"(b[1]));
}
__device__ __forceinline__ void mma_fp16(float* c, const uint32_t* a, const uint32_t* b) {
    asm volatile(
        "mma.sync.aligned.m16n8k16.row.col.f32.f16.f16.f32 "
        "{%0,%1,%2,%3}, {%4,%5,%6,%7}, {%8,%9}, {%0,%1,%2,%3};"
        : "+f"(c[0]), "+f"(c[1]), "+f"(c[2]), "+f"(c[3])
        : "r"(a[0]), "r"(a[1]), "r"(a[2]), "r"(a[3]), "r"(b[0]), "r"(b[1]));
}

// fp32 pair -> packed bf16x2 hi + lo
__device__ __forceinline__ void pack_hl(float a, float b, uint32_t& hi, uint32_t& lo) {
    __nv_bfloat16 h0 = __float2bfloat16(a);
    __nv_bfloat16 h1 = __float2bfloat16(b);
    __nv_bfloat16 l0 = __float2bfloat16(a - __bfloat162float(h0));
    __nv_bfloat16 l1 = __float2bfloat16(b - __bfloat162float(h1));
    __nv_bfloat162 ph; ph.x = h0; ph.y = h1;
    __nv_bfloat162 pl; pl.x = l0; pl.y = l1;
    hi = *(uint32_t*)&ph;
    lo = *(uint32_t*)&pl;
}
// fp32 pair -> packed fp16x2 hi + lo
__device__ __forceinline__ void pack_hl_f16(float a, float b, uint32_t& hi, uint32_t& lo) {
    __half h0 = __float2half(a);
    __half h1 = __float2half(b);
    __half l0 = __float2half(a - __half2float(h0));
    __half l1 = __float2half(b - __half2float(h1));
    __half2 ph; ph.x = h0; ph.y = h1;
    __half2 pl; pl.x = l0; pl.y = l1;
    hi = *(uint32_t*)&ph;
    lo = *(uint32_t*)&pl;
}

// ---------------------------------------------------------------------------
// fp16 2-term HMMA GEMM: C = A[M,K] @ W + bias (W transposed as B[N,K]).
// A split into fp16 hi+lo (exact to 2^-22); B single fp16 (err ~1.5e-4).
// Terms: Ahi*B + Alo*B.  CTA 128x128, BK=32, 8 warps of 64x32,
// 3-stage cp.async, 2 CTAs/SM.
// Output: fp32 (Cf) OR split bf16 hi/lo with 2^-3 scale on first qcols cols.
// ---------------------------------------------------------------------------
#define PITCH 40                          // bf16/fp16 elems per smem row (32+8)
#define TILE_B (128 * PITCH * 2)          // 10240 bytes per tile
#define STAGE_B (3 * TILE_B)              // Ahi|Alo|Bhi = 30720
#define GEMM_SMEM (3 * STAGE_B)           // 92160 (x2 CTAs = 184320 <= 227KB)

__global__ void __launch_bounds__(256, 2)
mma_gemm_kernel(const __half* __restrict__ Ahi,
                const __half* __restrict__ Alo,
                const __half* __restrict__ Bhi,
                const float* __restrict__ bias,
                float* __restrict__ Cf,
                __nv_bfloat16* __restrict__ Chi, __nv_bfloat16* __restrict__ Clo,
                int qcols, int M, int N, int K)
{
    extern __shared__ char smem[];
    const uint32_t sb = smem_u32(smem);
    const int tid = threadIdx.x;
    const int wid = tid >> 5;
    const int lid = tid & 31;
    const int bm = blockIdx.y * 128;
    const int bn = blockIdx.x * 128;
    const int m0 = (wid >> 2) * 64;
    const int n0 = (wid & 3) * 32;
    const int NCH = K / 32;

    float acc[4][4][4];
#pragma unroll
    for (int i = 0; i < 4; i++)
#pragma unroll
        for (int j = 0; j < 4; j++)
#pragma unroll
            for (int r = 0; r < 4; r++) acc[i][j][r] = 0.0f;

    auto cp_tile = [&](const __half* g, int row0, int kc, uint32_t sdst) {
#pragma unroll
        for (int it = 0; it < 2; ++it) {
            int idx = tid + it * 256;
            int r = idx >> 2;
            int u = idx & 3;
            const __half* src = g + (size_t)(row0 + r) * K + kc + u * 8;
            CP_ASYNC16(sdst + (r * PITCH + u * 8) * 2, src);
        }
    };
    auto load_stage = [&](int c, int stg) {
        uint32_t base = sb + stg * STAGE_B;
        int kc = c * 32;
        cp_tile(Ahi, bm, kc, base);
        cp_tile(Alo, bm, kc, base + TILE_B);
        cp_tile(Bhi, bn, kc, base + 2 * TILE_B);
    };

    load_stage(0, 0);
    CP_COMMIT();
    load_stage(1, 1);
    CP_COMMIT();

    const int a_row = lid & 15;
    const int a_k   = lid >> 4;
    const int b_row = lid & 7;
    const int b_k   = (lid >> 3) & 1;

    for (int c = 0; c < NCH; ++c) {
        if (c + 2 < NCH) {
            load_stage(c + 2, (c + 2) % 3);
            CP_COMMIT();
            CP_WAIT(2);
        } else {
            CP_WAIT(0);
        }
        __syncthreads();

        const uint32_t base = sb + (c % 3) * STAGE_B;
        const uint32_t pa_hi = base + ((m0 + a_row) * PITCH + a_k * 8) * 2;
        const uint32_t pa_lo = pa_hi + TILE_B;
        const uint32_t pb_hi = base + 2 * TILE_B + ((n0 + b_row) * PITCH + b_k * 8) * 2;

#pragma unroll
        for (int ks = 0; ks < 2; ++ks) {
            const uint32_t ko = ks * 32;
            // hoist B fragments for this k-step
            uint32_t Bh[4][2];
#pragma unroll
            for (int nf = 0; nf < 4; ++nf)
                LDSM_X2(Bh[nf][0], Bh[nf][1], pb_hi + ko + nf * (8 * PITCH * 2));
            // stream A fragments one mf at a time; RAW distance 4 via nf loop
#pragma unroll
            for (int mf = 0; mf < 4; ++mf) {
                uint32_t Ah[4], Al[4];
                uint32_t off = ko + mf * (16 * PITCH * 2);
                LDSM_X4(Ah[0], Ah[1], Ah[2], Ah[3], pa_hi + off);
                LDSM_X4(Al[0], Al[1], Al[2], Al[3], pa_lo + off);
#pragma unroll
                for (int nf = 0; nf < 4; ++nf) mma_fp16(acc[mf][nf], Ah, Bh[nf]);
#pragma unroll
                for (int nf = 0; nf < 4; ++nf) mma_fp16(acc[mf][nf], Al, Bh[nf]);
            }
        }
        __syncthreads();
    }

    // Epilogue
    const int grow = lid >> 2;
    const int gcol = (lid & 3) * 2;
#pragma unroll
    for (int mf = 0; mf < 4; ++mf) {
#pragma unroll
        for (int nf = 0; nf < 4; ++nf) {
            int r0  = bm + m0 + mf * 16 + grow;
            int col = bn + n0 + nf * 8 + gcol;
            float b0 = bias[col], b1 = bias[col + 1];
            float v0 = acc[mf][nf][0] + b0, v1 = acc[mf][nf][1] + b1;
            float v2 = acc[mf][nf][2] + b0, v3 = acc[mf][nf][3] + b1;
            if (Cf) {
                *(float2*)&Cf[(size_t)r0 * N + col]       = make_float2(v0, v1);
                *(float2*)&Cf[(size_t)(r0 + 8) * N + col] = make_float2(v2, v3);
            } else {
                if (col < qcols) { v0 *= 0.125f; v1 *= 0.125f; v2 *= 0.125f; v3 *= 0.125f; }
                uint32_t h01, l01, h23, l23;
                pack_hl(v0, v1, h01, l01);
                pack_hl(v2, v3, h23, l23);
                *(uint32_t*)&Chi[(size_t)r0 * N + col]       = h01;
                *(uint32_t*)&Clo[(size_t)r0 * N + col]       = l01;
                *(uint32_t*)&Chi[(size_t)(r0 + 8) * N + col] = h23;
                *(uint32_t*)&Clo[(size_t)(r0 + 8) * N + col] = l23;
            }
        }
    }
}

// ---------------------------------------------------------------------------
// fp32 -> (fp16 hi, fp16 lo) split, vectorized
// ---------------------------------------------------------------------------
__global__ void __launch_bounds__(256)
split_f16_kernel(const float* __restrict__ in, __half* __restrict__ hi,
                 __half* __restrict__ lo, int n4)
{
    int i = blockIdx.x * blockDim.x + threadIdx.x;
    if (i >= n4) return;
    float4 v = ((const float4*)in)[i];
    uint32_t h01, l01, h23, l23;
    pack_hl_f16(v.x, v.y, h01, l01);
    pack_hl_f16(v.z, v.w, h23, l23);
    ((uint32_t*)hi)[2 * i]     = h01;
    ((uint32_t*)hi)[2 * i + 1] = h23;
    ((uint32_t*)lo)[2 * i]     = l01;
    ((uint32_t*)lo)[2 * i + 1] = l23;
}

// ---------------------------------------------------------------------------
// W[K][N] fp32 -> T[N][K] fp16 (hi only; tiled transpose)
// ---------------------------------------------------------------------------
__global__ void __launch_bounds__(256)
transpose_f16_kernel(const float* __restrict__ W, __half* __restrict__ Thi,
                     int K, int N)
{
    __shared__ float t[32][33];
    const int n0 = blockIdx.x * 32;
    const int k0 = blockIdx.y * 32;
    const int tx = threadIdx.x, ty = threadIdx.y;
#pragma unroll
    for (int j = 0; j < 4; ++j)
        t[ty + j * 8][tx] = W[(size_t)(k0 + ty + j * 8) * N + n0 + tx];
    __syncthreads();
#pragma unroll
    for (int j = 0; j < 4; ++j) {
        int n = n0 + ty + j * 8;
        int k = k0 + tx;
        Thi[(size_t)n * K + k] = __float2half(t[tx][ty + j * 8]);
    }
}

// ---------------------------------------------------------------------------
// HMMA causal flash attention (bf16 3-term, unchanged math).
// Inputs: qkv bf16 hi/lo (Q pre-scaled 2^-3). Outputs: y fp16 hi/lo.
// APITCH = 72 (row stride 144 B -> conflict-free ldmatrix).
// ---------------------------------------------------------------------------
#define APITCH 72
#define AT_QTILE_B (128 * APITCH * 2)    // 18432
#define AT_KTILE_B (64 * APITCH * 2)     // 9216
#define AT_STAGE_B (4 * AT_KTILE_B)      // 36864
#define AT_SMEM (2 * AT_QTILE_B + 2 * AT_STAGE_B)   // 110592

__global__ void __launch_bounds__(256, 1)
attn_mma_kernel(const __nv_bfloat16* __restrict__ qvh,
                const __nv_bfloat16* __restrict__ qvl,
                __half* __restrict__ yhi, __half* __restrict__ ylo)
{
    extern __shared__ char smem[];
    const uint32_t sb = smem_u32(smem);
    const int tid = threadIdx.x, wid = tid >> 5, lid = tid & 31;
    const int qt = gridDim.x - 1 - blockIdx.x;   // heavy tiles launch first
    const int bh = blockIdx.y, b = bh / HH, h = bh % HH;
    const int q0 = qt * 128;
    const uint32_t sQh = sb, sQl = sb + AT_QTILE_B;
    const uint32_t sStage = sb + 2 * AT_QTILE_B;
    const size_t rowbase = (size_t)b * TT * N_QKV + h * DD;

    // Q tile load (hi/lo), 128 rows x 64 elems
#pragma unroll
    for (int it = 0; it < 4; ++it) {
        int idx = tid + it * 256;          // 0..1023
        int r = idx >> 3, u = idx & 7;
        size_t goff = rowbase + (size_t)(q0 + r) * N_QKV + u * 8;
        uint32_t d = (r * APITCH + u * 8) * 2;
        CP_ASYNC16(sQh + d, qvh + goff);
        CP_ASYNC16(sQl + d, qvl + goff);
    }

    auto load_kv = [&](int kt) {
        uint32_t base = sStage + (kt & 1) * AT_STAGE_B;
        int k0 = kt * 64;
#pragma unroll
        for (int it = 0; it < 8; ++it) {
            int idx = tid + it * 256;      // 0..2047
            int tile = idx >> 9, rem = idx & 511;
            int r = rem >> 3, u = rem & 7;
            const __nv_bfloat16* sp = (tile & 1) ? qvl : qvh;
            int coff = (tile < 2) ? CC : 2 * CC;
            const __nv_bfloat16* src = sp + rowbase + (size_t)(k0 + r) * N_QKV + coff + u * 8;
            CP_ASYNC16(base + tile * AT_KTILE_B + (r * APITCH + u * 8) * 2, src);
        }
    };

    const int nkt = 2 * qt + 2;
    load_kv(0);
    CP_COMMIT();
    load_kv(1);
    CP_COMMIT();
    CP_WAIT(1);
    __syncthreads();

    // hoist Q fragments (loop-invariant)
    uint32_t qfh[4][4], qfl[4][4];
    {
        const int a_row = lid & 15, a_k = lid >> 4;
        uint32_t ah = sQh + ((wid * 16 + a_row) * APITCH + a_k * 8) * 2;
        uint32_t al = sQl + ((wid * 16 + a_row) * APITCH + a_k * 8) * 2;
#pragma unroll
        for (int ks = 0; ks < 4; ++ks) {
            LDSM_X4(qfh[ks][0], qfh[ks][1], qfh[ks][2], qfh[ks][3], ah + ks * 32);
            LDSM_X4(qfl[ks][0], qfl[ks][1], qfl[ks][2], qfl[ks][3], al + ks * 32);
        }
    }

    float oacc[8][4];
#pragma unroll
    for (int nf = 0; nf < 8; ++nf)
#pragma unroll
        for (int r = 0; r < 4; ++r) oacc[nf][r] = 0.0f;
    float mrow0 = -1e30f, mrow1 = -1e30f, lrow0 = 0.0f, lrow1 = 0.0f;

    const int b_row = lid & 7, b_k = (lid >> 3) & 1;
    const int v_row = lid & 15;
    const int rloc  = lid >> 2;

    for (int kt = 0; kt < nkt; ++kt) {
        if (kt > 0) {
            if (kt + 1 < nkt) CP_WAIT(1); else CP_WAIT(0);
            __syncthreads();
        }
        const int k0 = kt * 64;
        const uint32_t stg = sStage + (kt & 1) * AT_STAGE_B;

        if (k0 <= q0 + wid * 16 + 15) {      // warp-uniform causal skip
            // ---- S = Q K^T (3-term split) ----
            float sa[8][4];
#pragma unroll
            for (int nf = 0; nf < 8; ++nf)
#pragma unroll
                for (int r = 0; r < 4; ++r) sa[nf][r] = 0.0f;

            const uint32_t kh_base = stg + (b_row * APITCH + b_k * 8) * 2;
            const uint32_t kl_base = kh_base + AT_KTILE_B;
#pragma unroll
            for (int nf = 0; nf < 8; ++nf) {
                uint32_t oh = kh_base + nf * (8 * APITCH * 2);
                uint32_t ol = kl_base + nf * (8 * APITCH * 2);
#pragma unroll
                for (int ks = 0; ks < 4; ++ks) {
                    uint32_t Bh[2], Bl[2];
                    LDSM_X2(Bh[0], Bh[1], oh + ks * 32);
                    LDSM_X2(Bl[0], Bl[1], ol + ks * 32);
                    mma_bf16(sa[nf], qfh[ks], Bh);
                    mma_bf16(sa[nf], qfh[ks], Bl);
                    mma_bf16(sa[nf], qfl[ks], Bh);
                }
            }

            const int rg0 = q0 + wid * 16 + rloc;
            const int rg1 = rg0 + 8;
            if (k0 + 63 > q0 + wid * 16) {   // diagonal tile: mask
#pragma unroll
                for (int nf = 0; nf < 8; ++nf) {
                    int c0 = k0 + nf * 8 + 2 * (lid & 3);
                    if (c0     > rg0) sa[nf][0] = -1e30f;
                    if (c0 + 1 > rg0) sa[nf][1] = -1e30f;
                    if (c0     > rg1) sa[nf][2] = -1e30f;
                    if (c0 + 1 > rg1) sa[nf][3] = -1e30f;
                }
            }

            // ---- online softmax (rows rloc, rloc+8; quad reduce) ----
            float mx0 = -1e30f, mx1 = -1e30f;
#pragma unroll
            for (int nf = 0; nf < 8; ++nf) {
                mx0 = fmaxf(mx0, fmaxf(sa[nf][0], sa[nf][1]));
                mx1 = fmaxf(mx1, fmaxf(sa[nf][2], sa[nf][3]));
            }
            mx0 = fmaxf(mx0, __shfl_xor_sync(0xffffffffu, mx0, 1));
            mx0 = fmaxf(mx0, __shfl_xor_sync(0xffffffffu, mx0, 2));
            mx1 = fmaxf(mx1, __shfl_xor_sync(0xffffffffu, mx1, 1));
            mx1 = fmaxf(mx1, __shfl_xor_sync(0xffffffffu, mx1, 2));
            float mn0 = fmaxf(mrow0, mx0), mn1 = fmaxf(mrow1, mx1);
            float corr0 = __expf(mrow0 - mn0), corr1 = __expf(mrow1 - mn1);
            float sum0 = 0.0f, sum1 = 0.0f;
#pragma unroll
            for (int nf = 0; nf < 8; ++nf) {
                sa[nf][0] = __expf(sa[nf][0] - mn0);
                sa[nf][1] = __expf(sa[nf][1] - mn0);
                sa[nf][2] = __expf(sa[nf][2] - mn1);
                sa[nf][3] = __expf(sa[nf][3] - mn1);
                sum0 += sa[nf][0] + sa[nf][1];
                sum1 += sa[nf][2] + sa[nf][3];
            }
            sum0 += __shfl_xor_sync(0xffffffffu, sum0, 1);
            sum0 += __shfl_xor_sync(0xffffffffu, sum0, 2);
            sum1 += __shfl_xor_sync(0xffffffffu, sum1, 1);
            sum1 += __shfl_xor_sync(0xffffffffu, sum1, 2);
            lrow0 = lrow0 * corr0 + sum0;
            lrow1 = lrow1 * corr1 + sum1;
            mrow0 = mn0; mrow1 = mn1;
#pragma unroll
            for (int nf = 0; nf < 8; ++nf) {
                oacc[nf][0] *= corr0; oacc[nf][1] *= corr0;
                oacc[nf][2] *= corr1; oacc[nf][3] *= corr1;
            }

            // ---- pack P c-frags -> A-frags (hi/lo) ----
            uint32_t pah[4][4], pal[4][4];
#pragma unroll
            for (int ks = 0; ks < 4; ++ks) {
                pack_hl(sa[2 * ks][0],     sa[2 * ks][1],     pah[ks][0], pal[ks][0]);
                pack_hl(sa[2 * ks][2],     sa[2 * ks][3],     pah[ks][1], pal[ks][1]);
                pack_hl(sa[2 * ks + 1][0], sa[2 * ks + 1][1], pah[ks][2], pal[ks][2]);
                pack_hl(sa[2 * ks + 1][2], sa[2 * ks + 1][3], pah[ks][3], pal[ks][3]);
            }

            // ---- O += P V (3-term split); V b-frags via ldmatrix.trans ----
            const uint32_t vh_base = stg + 2 * AT_KTILE_B + (v_row * APITCH) * 2;
            const uint32_t vl_base = vh_base + AT_KTILE_B;
#pragma unroll
            for (int nf = 0; nf < 8; ++nf) {
#pragma unroll
                for (int ks = 0; ks < 4; ++ks) {
                    uint32_t Bh[2], Bl[2];
                    uint32_t off = (ks * 16 * APITCH + nf * 8) * 2;
                    LDSM_X2_T(Bh[0], Bh[1], vh_base + off);
                    LDSM_X2_T(Bl[0], Bl[1], vl_base + off);
                    mma_bf16(oacc[nf], pah[ks], Bh);
                    mma_bf16(oacc[nf], pah[ks], Bl);
                    mma_bf16(oacc[nf], pal[ks], Bh);
                }
            }
        }
        __syncthreads();
        if (kt + 2 < nkt) { load_kv(kt + 2); CP_COMMIT(); }
    }

    // ---- epilogue: normalize and write y fp16 hi/lo ----
    const float inv0 = 1.0f / lrow0, inv1 = 1.0f / lrow1;
    const int rg0 = q0 + wid * 16 + rloc;
    const size_t y0 = ((size_t)(b * TT) + rg0) * CC + h * DD;
    const size_t y1 = y0 + 8 * CC;
#pragma unroll
    for (int nf = 0; nf < 8; ++nf) {
        int col = nf * 8 + 2 * (lid & 3);
        uint32_t h01, l01, h23, l23;
        pack_hl_f16(oacc[nf][0] * inv0, oacc[nf][1] * inv0, h01, l01);
        pack_hl_f16(oacc[nf][2] * inv1, oacc[nf][3] * inv1, h23, l23);
        *(uint32_t*)&yhi[y0 + col] = h01;
        *(uint32_t*)&ylo[y0 + col] = l01;
        *(uint32_t*)&yhi[y1 + col] = h23;
        *(uint32_t*)&ylo[y1 + col] = l23;
    }
}

// ---------------------------------------------------------------------------
// Launch
// ---------------------------------------------------------------------------
extern "C" void kernel_launch(void* const* d_in, const int* in_sizes, int n_in,
                              void* d_out, int out_size)
{
    const float* x     = (const float*)d_in[0];
    const float* wqkv  = (const float*)d_in[1];
    const float* bqkv  = (const float*)d_in[2];
    const float* wproj = (const float*)d_in[3];
    const float* bproj = (const float*)d_in[4];
    float* out = (float*)d_out;

    __nv_bfloat16 *qkh, *qkl;
    __half *xh, *xl, *wqh, *wph, *yh, *yl;
    cudaGetSymbolAddress((void**)&qkh, g_qkv_hi);
    cudaGetSymbolAddress((void**)&qkl, g_qkv_lo);
    cudaGetSymbolAddress((void**)&xh,  g_x_hi);
    cudaGetSymbolAddress((void**)&xl,  g_x_lo);
    cudaGetSymbolAddress((void**)&wqh, g_wq_hi);
    cudaGetSymbolAddress((void**)&wph, g_wp_hi);
    cudaGetSymbolAddress((void**)&yh,  g_y_hi);
    cudaGetSymbolAddress((void**)&yl,  g_y_lo);

    cudaFuncSetAttribute(mma_gemm_kernel,
                         cudaFuncAttributeMaxDynamicSharedMemorySize, GEMM_SMEM);
    cudaFuncSetAttribute(attn_mma_kernel,
                         cudaFuncAttributeMaxDynamicSharedMemorySize, AT_SMEM);

    // Prep: split x (fp16); transpose both weight matrices to fp16 hi
    split_f16_kernel<<<(M_ROWS * CC / 4 + 255) / 256, 256>>>(x, xh, xl, M_ROWS * CC / 4);
    transpose_f16_kernel<<<dim3(N_QKV / 32, CC / 32), dim3(32, 8)>>>(wqkv, wqh, CC, N_QKV);
    transpose_f16_kernel<<<dim3(CC / 32, CC / 32), dim3(32, 8)>>>(wproj, wph, CC, CC);

    // 1) qkv = x @ Wqkv + b -> split bf16 hi/lo, q-columns pre-scaled by 2^-3
    mma_gemm_kernel<<<dim3(N_QKV / 128, M_ROWS / 128), 256, GEMM_SMEM>>>(
        xh, xl, wqh, bqkv, nullptr, qkh, qkl, CC, M_ROWS, N_QKV, CC);

    // 2) HMMA causal flash attention -> y fp16 hi/lo
    attn_mma_kernel<<<dim3(TT / 128, BB * HH), 256, AT_SMEM>>>(qkh, qkl, yh, yl);

    // 3) out = y @ Wproj + b  (fp32 output)
    mma_gemm_kernel<<<dim3(CC / 128, M_ROWS / 128), 256, GEMM_SMEM>>>(
        yh, yl, wph, bproj, out, nullptr, nullptr, 0, M_ROWS, CC, CC);
}

// round 16
// speedup vs baseline: 3.8194x; 1.2363x over previous
#include <cuda_runtime.h>
#include <cuda_bf16.h>
#include <cuda_fp16.h>
#include <cstdint>
#include <math.h>

// Problem constants
#define BB 8
#define TT 1024
#define CC 768
#define HH 12
#define DD 64
#define M_ROWS (BB * TT)          // 8192
#define N_QKV  (3 * CC)           // 2304

// ---------------------------------------------------------------------------
// Scratch (device globals; runtime allocation is forbidden)
// ---------------------------------------------------------------------------
__device__ __half g_qkv_hi[M_ROWS * N_QKV];   // GEMM1 out (fp16)
__device__ __half g_qkv_lo[M_ROWS * N_QKV];   // lo written for Q cols only
__device__ __half g_x_hi[M_ROWS * CC];        // x split (fp16)
__device__ __half g_x_lo[M_ROWS * CC];
__device__ __half g_wq_hi[N_QKV * CC];        // Wqkv^T fp16
__device__ __half g_wp_hi[CC * CC];           // Wproj^T fp16
__device__ __half g_y_hi[M_ROWS * CC];        // attention out (fp16 split)
__device__ __half g_y_lo[M_ROWS * CC];

// ---------------------------------------------------------------------------
// Portable tensor-core helpers: mma.sync + ldmatrix + cp.async
// ---------------------------------------------------------------------------
__device__ __forceinline__ uint32_t smem_u32(const void* p) {
    uint32_t a;
    asm("{ .reg .u64 t; cvta.to.shared.u64 t, %1; cvt.u32.u64 %0, t; }"
        : "=r"(a) : "l"(p));
    return a;
}

#define CP_ASYNC16(dst, src) \
    asm volatile("cp.async.cg.shared.global [%0], [%1], 16;" \
                 :: "r"(dst), "l"(src) : "memory")
#define CP_COMMIT() asm volatile("cp.async.commit_group;" ::: "memory")
#define CP_WAIT(n)  asm volatile("cp.async.wait_group %0;" :: "n"(n) : "memory")

#define LDSM_X4(r0, r1, r2, r3, addr) \
    asm volatile("ldmatrix.sync.aligned.m8n8.x4.shared.b16 {%0,%1,%2,%3}, [%4];" \
                 : "=r"(r0), "=r"(r1), "=r"(r2), "=r"(r3) : "r"(addr))
#define LDSM_X2(r0, r1, addr) \
    asm volatile("ldmatrix.sync.aligned.m8n8.x2.shared.b16 {%0,%1}, [%2];" \
                 : "=r"(r0), "=r"(r1) : "r"(addr))
#define LDSM_X2_T(r0, r1, addr) \
    asm volatile("ldmatrix.sync.aligned.m8n8.x2.trans.shared.b16 {%0,%1}, [%2];" \
                 : "=r"(r0), "=r"(r1) : "r"(addr))

__device__ __forceinline__ void mma_fp16(float* c, const uint32_t* a, const uint32_t* b) {
    asm volatile(
        "mma.sync.aligned.m16n8k16.row.col.f32.f16.f16.f32 "
        "{%0,%1,%2,%3}, {%4,%5,%6,%7}, {%8,%9}, {%0,%1,%2,%3};"
        : "+f"(c[0]), "+f"(c[1]), "+f"(c[2]), "+f"(c[3])
        : "r"(a[0]), "r"(a[1]), "r"(a[2]), "r"(a[3]), "r"(b[0]), "r"(b[1]));
}

// fp32 pair -> packed fp16x2 hi + lo
__device__ __forceinline__ void pack_hl_f16(float a, float b, uint32_t& hi, uint32_t& lo) {
    __half h0 = __float2half(a);
    __half h1 = __float2half(b);
    __half l0 = __float2half(a - __half2float(h0));
    __half l1 = __float2half(b - __half2float(h1));
    __half2 ph; ph.x = h0; ph.y = h1;
    __half2 pl; pl.x = l0; pl.y = l1;
    hi = *(uint32_t*)&ph;
    lo = *(uint32_t*)&pl;
}

// ---------------------------------------------------------------------------
// fp16 2-term HMMA GEMM: C = A[M,K] @ W + bias (W transposed as B[N,K]).
// Terms: Ahi*B + Alo*B (A split exact; B single fp16, err ~2.7e-4).
// CTA 128x128, BK=64 (12 chunks: half the barrier events), 8 warps of
// 64x32, 2-stage cp.async, 2 CTAs/SM (221KB smem total).
// Output: fp32 (Cf) OR split fp16 hi/lo; first qcols cols scaled 2^-3 and
// the ONLY cols whose lo is written (K/V consumed as single fp16).
// ---------------------------------------------------------------------------
#define GP 72                             // fp16 elems per smem row (64 + 8)
#define GTILE_B (128 * GP * 2)            // 18432 bytes per tile
#define GSTAGE_B (3 * GTILE_B)            // Ahi|Alo|Bhi = 55296
#define GEMM_SMEM (2 * GSTAGE_B)          // 110592 (x2 CTAs = 221184)

__global__ void __launch_bounds__(256, 2)
mma_gemm_kernel(const __half* __restrict__ Ahi,
                const __half* __restrict__ Alo,
                const __half* __restrict__ Bhi,
                const float* __restrict__ bias,
                float* __restrict__ Cf,
                __half* __restrict__ Chi, __half* __restrict__ Clo,
                int qcols, int M, int N, int K)
{
    extern __shared__ char smem[];
    const uint32_t sb = smem_u32(smem);
    const int tid = threadIdx.x;
    const int wid = tid >> 5;
    const int lid = tid & 31;
    const int bm = blockIdx.y * 128;
    const int bn = blockIdx.x * 128;
    const int m0 = (wid >> 2) * 64;
    const int n0 = (wid & 3) * 32;
    const int NCH = K / 64;

    float acc[4][4][4];
#pragma unroll
    for (int i = 0; i < 4; i++)
#pragma unroll
        for (int j = 0; j < 4; j++)
#pragma unroll
            for (int r = 0; r < 4; r++) acc[i][j][r] = 0.0f;

    auto cp_tile = [&](const __half* g, int row0, int kc, uint32_t sdst) {
#pragma unroll
        for (int it = 0; it < 4; ++it) {
            int idx = tid + it * 256;     // 0..1023
            int r = idx >> 3;
            int u = idx & 7;
            const __half* src = g + (size_t)(row0 + r) * K + kc + u * 8;
            CP_ASYNC16(sdst + (r * GP + u * 8) * 2, src);
        }
    };
    auto load_stage = [&](int c, int stg) {
        uint32_t base = sb + stg * GSTAGE_B;
        int kc = c * 64;
        cp_tile(Ahi, bm, kc, base);
        cp_tile(Alo, bm, kc, base + GTILE_B);
        cp_tile(Bhi, bn, kc, base + 2 * GTILE_B);
    };

    load_stage(0, 0);
    CP_COMMIT();

    const int a_row = lid & 15;
    const int a_k   = lid >> 4;
    const int b_row = lid & 7;
    const int b_k   = (lid >> 3) & 1;

    for (int c = 0; c < NCH; ++c) {
        if (c + 1 < NCH) {
            load_stage(c + 1, (c + 1) & 1);
            CP_COMMIT();
            CP_WAIT(1);
        } else {
            CP_WAIT(0);
        }
        __syncthreads();

        const uint32_t base = sb + (c & 1) * GSTAGE_B;
        const uint32_t pa_hi = base + ((m0 + a_row) * GP + a_k * 8) * 2;
        const uint32_t pa_lo = pa_hi + GTILE_B;
        const uint32_t pb_hi = base + 2 * GTILE_B + ((n0 + b_row) * GP + b_k * 8) * 2;

#pragma unroll
        for (int ks = 0; ks < 4; ++ks) {
            const uint32_t ko = ks * 32;  // 16 fp16 = 32 bytes per k-step
            uint32_t Bh[4][2];
#pragma unroll
            for (int nf = 0; nf < 4; ++nf)
                LDSM_X2(Bh[nf][0], Bh[nf][1], pb_hi + ko + nf * (8 * GP * 2));
#pragma unroll
            for (int mf = 0; mf < 4; ++mf) {
                uint32_t Ah[4], Al[4];
                uint32_t off = ko + mf * (16 * GP * 2);
                LDSM_X4(Ah[0], Ah[1], Ah[2], Ah[3], pa_hi + off);
                LDSM_X4(Al[0], Al[1], Al[2], Al[3], pa_lo + off);
#pragma unroll
                for (int nf = 0; nf < 4; ++nf) mma_fp16(acc[mf][nf], Ah, Bh[nf]);
#pragma unroll
                for (int nf = 0; nf < 4; ++nf) mma_fp16(acc[mf][nf], Al, Bh[nf]);
            }
        }
        __syncthreads();
    }

    // Epilogue
    const int grow = lid >> 2;
    const int gcol = (lid & 3) * 2;
#pragma unroll
    for (int mf = 0; mf < 4; ++mf) {
#pragma unroll
        for (int nf = 0; nf < 4; ++nf) {
            int r0  = bm + m0 + mf * 16 + grow;
            int col = bn + n0 + nf * 8 + gcol;
            float b0 = bias[col], b1 = bias[col + 1];
            float v0 = acc[mf][nf][0] + b0, v1 = acc[mf][nf][1] + b1;
            float v2 = acc[mf][nf][2] + b0, v3 = acc[mf][nf][3] + b1;
            if (Cf) {
                *(float2*)&Cf[(size_t)r0 * N + col]       = make_float2(v0, v1);
                *(float2*)&Cf[(size_t)(r0 + 8) * N + col] = make_float2(v2, v3);
            } else {
                bool isq = (col < qcols);
                if (isq) { v0 *= 0.125f; v1 *= 0.125f; v2 *= 0.125f; v3 *= 0.125f; }
                uint32_t h01, l01, h23, l23;
                pack_hl_f16(v0, v1, h01, l01);
                pack_hl_f16(v2, v3, h23, l23);
                *(uint32_t*)&Chi[(size_t)r0 * N + col]       = h01;
                *(uint32_t*)&Chi[(size_t)(r0 + 8) * N + col] = h23;
                if (isq) {
                    *(uint32_t*)&Clo[(size_t)r0 * N + col]       = l01;
                    *(uint32_t*)&Clo[(size_t)(r0 + 8) * N + col] = l23;
                }
            }
        }
    }
}

// ---------------------------------------------------------------------------
// fp32 -> (fp16 hi, fp16 lo) split, vectorized
// ---------------------------------------------------------------------------
__global__ void __launch_bounds__(256)
split_f16_kernel(const float* __restrict__ in, __half* __restrict__ hi,
                 __half* __restrict__ lo, int n4)
{
    int i = blockIdx.x * blockDim.x + threadIdx.x;
    if (i >= n4) return;
    float4 v = ((const float4*)in)[i];
    uint32_t h01, l01, h23, l23;
    pack_hl_f16(v.x, v.y, h01, l01);
    pack_hl_f16(v.z, v.w, h23, l23);
    ((uint32_t*)hi)[2 * i]     = h01;
    ((uint32_t*)hi)[2 * i + 1] = h23;
    ((uint32_t*)lo)[2 * i]     = l01;
    ((uint32_t*)lo)[2 * i + 1] = l23;
}

// ---------------------------------------------------------------------------
// W[K][N] fp32 -> T[N][K] fp16 (hi only; tiled transpose)
// ---------------------------------------------------------------------------
__global__ void __launch_bounds__(256)
transpose_f16_kernel(const float* __restrict__ W, __half* __restrict__ Thi,
                     int K, int N)
{
    __shared__ float t[32][33];
    const int n0 = blockIdx.x * 32;
    const int k0 = blockIdx.y * 32;
    const int tx = threadIdx.x, ty = threadIdx.y;
#pragma unroll
    for (int j = 0; j < 4; ++j)
        t[ty + j * 8][tx] = W[(size_t)(k0 + ty + j * 8) * N + n0 + tx];
    __syncthreads();
#pragma unroll
    for (int j = 0; j < 4; ++j) {
        int n = n0 + ty + j * 8;
        int k = k0 + tx;
        Thi[(size_t)n * K + k] = __float2half(t[tx][ty + j * 8]);
    }
}

// ---------------------------------------------------------------------------
// fp16 HMMA causal flash attention, 2-term on both GEMMs:
//   S = Qhi K + Qlo K   (K single fp16)
//   O += Phi V + Plo V  (V single fp16)
// q-tile 128 (8 warps x 16 rows), k-tile 64, Q pre-scaled 2^-3 upstream.
// KV stage = 2 tiles (half of round-14 traffic). APITCH=72 conflict-free.
// ---------------------------------------------------------------------------
#define APITCH 72
#define AT_QTILE_B (128 * APITCH * 2)    // 18432
#define AT_KTILE_B (64 * APITCH * 2)     // 9216
#define AT_STAGE_B (2 * AT_KTILE_B)      // 18432 (K|V)
#define AT_SMEM (2 * AT_QTILE_B + 2 * AT_STAGE_B)   // 73728

__global__ void __launch_bounds__(256, 1)
attn_mma_kernel(const __half* __restrict__ qvh,
                const __half* __restrict__ qvl,
                __half* __restrict__ yhi, __half* __restrict__ ylo)
{
    extern __shared__ char smem[];
    const uint32_t sb = smem_u32(smem);
    const int tid = threadIdx.x, wid = tid >> 5, lid = tid & 31;
    const int qt = gridDim.x - 1 - blockIdx.x;   // heavy tiles launch first
    const int bh = blockIdx.y, b = bh / HH, h = bh % HH;
    const int q0 = qt * 128;
    const uint32_t sQh = sb, sQl = sb + AT_QTILE_B;
    const uint32_t sStage = sb + 2 * AT_QTILE_B;
    const size_t rowbase = (size_t)b * TT * N_QKV + h * DD;

    // Q tile load (hi/lo), 128 rows x 64 elems
#pragma unroll
    for (int it = 0; it < 4; ++it) {
        int idx = tid + it * 256;          // 0..1023
        int r = idx >> 3, u = idx & 7;
        size_t goff = rowbase + (size_t)(q0 + r) * N_QKV + u * 8;
        uint32_t d = (r * APITCH + u * 8) * 2;
        CP_ASYNC16(sQh + d, qvh + goff);
        CP_ASYNC16(sQl + d, qvl + goff);
    }

    auto load_kv = [&](int kt) {
        uint32_t base = sStage + (kt & 1) * AT_STAGE_B;
        int k0 = kt * 64;
#pragma unroll
        for (int it = 0; it < 4; ++it) {
            int idx = tid + it * 256;      // 0..1023
            int tile = idx >> 9, rem = idx & 511;   // tile 0=K, 1=V
            int r = rem >> 3, u = rem & 7;
            int coff = (tile == 0) ? CC : 2 * CC;
            const __half* src = qvh + rowbase + (size_t)(k0 + r) * N_QKV + coff + u * 8;
            CP_ASYNC16(base + tile * AT_KTILE_B + (r * APITCH + u * 8) * 2, src);
        }
    };

    const int nkt = 2 * qt + 2;
    load_kv(0);
    CP_COMMIT();
    load_kv(1);
    CP_COMMIT();
    CP_WAIT(1);
    __syncthreads();

    // hoist Q fragments (loop-invariant)
    uint32_t qfh[4][4], qfl[4][4];
    {
        const int a_row = lid & 15, a_k = lid >> 4;
        uint32_t ah = sQh + ((wid * 16 + a_row) * APITCH + a_k * 8) * 2;
        uint32_t al = sQl + ((wid * 16 + a_row) * APITCH + a_k * 8) * 2;
#pragma unroll
        for (int ks = 0; ks < 4; ++ks) {
            LDSM_X4(qfh[ks][0], qfh[ks][1], qfh[ks][2], qfh[ks][3], ah + ks * 32);
            LDSM_X4(qfl[ks][0], qfl[ks][1], qfl[ks][2], qfl[ks][3], al + ks * 32);
        }
    }

    float oacc[8][4];
#pragma unroll
    for (int nf = 0; nf < 8; ++nf)
#pragma unroll
        for (int r = 0; r < 4; ++r) oacc[nf][r] = 0.0f;
    float mrow0 = -1e30f, mrow1 = -1e30f, lrow0 = 0.0f, lrow1 = 0.0f;

    const int b_row = lid & 7, b_k = (lid >> 3) & 1;
    const int v_row = lid & 15;
    const int rloc  = lid >> 2;

    for (int kt = 0; kt < nkt; ++kt) {
        if (kt > 0) {
            if (kt + 1 < nkt) CP_WAIT(1); else CP_WAIT(0);
            __syncthreads();
        }
        const int k0 = kt * 64;
        const uint32_t stg = sStage + (kt & 1) * AT_STAGE_B;

        if (k0 <= q0 + wid * 16 + 15) {      // warp-uniform causal skip
            // ---- S = Q K^T (fp16 2-term) ----
            float sa[8][4];
#pragma unroll
            for (int nf = 0; nf < 8; ++nf)
#pragma unroll
                for (int r = 0; r < 4; ++r) sa[nf][r] = 0.0f;

            const uint32_t kh_base = stg + (b_row * APITCH + b_k * 8) * 2;
#pragma unroll
            for (int nf = 0; nf < 8; ++nf) {
                uint32_t oh = kh_base + nf * (8 * APITCH * 2);
#pragma unroll
                for (int ks = 0; ks < 4; ++ks) {
                    uint32_t Bh[2];
                    LDSM_X2(Bh[0], Bh[1], oh + ks * 32);
                    mma_fp16(sa[nf], qfh[ks], Bh);
                    mma_fp16(sa[nf], qfl[ks], Bh);
                }
            }

            const int rg0 = q0 + wid * 16 + rloc;
            const int rg1 = rg0 + 8;
            if (k0 + 63 > q0 + wid * 16) {   // diagonal tile: mask
#pragma unroll
                for (int nf = 0; nf < 8; ++nf) {
                    int c0 = k0 + nf * 8 + 2 * (lid & 3);
                    if (c0     > rg0) sa[nf][0] = -1e30f;
                    if (c0 + 1 > rg0) sa[nf][1] = -1e30f;
                    if (c0     > rg1) sa[nf][2] = -1e30f;
                    if (c0 + 1 > rg1) sa[nf][3] = -1e30f;
                }
            }

            // ---- online softmax (rows rloc, rloc+8; quad reduce) ----
            float mx0 = -1e30f, mx1 = -1e30f;
#pragma unroll
            for (int nf = 0; nf < 8; ++nf) {
                mx0 = fmaxf(mx0, fmaxf(sa[nf][0], sa[nf][1]));
                mx1 = fmaxf(mx1, fmaxf(sa[nf][2], sa[nf][3]));
            }
            mx0 = fmaxf(mx0, __shfl_xor_sync(0xffffffffu, mx0, 1));
            mx0 = fmaxf(mx0, __shfl_xor_sync(0xffffffffu, mx0, 2));
            mx1 = fmaxf(mx1, __shfl_xor_sync(0xffffffffu, mx1, 1));
            mx1 = fmaxf(mx1, __shfl_xor_sync(0xffffffffu, mx1, 2));
            float mn0 = fmaxf(mrow0, mx0), mn1 = fmaxf(mrow1, mx1);
            float corr0 = __expf(mrow0 - mn0), corr1 = __expf(mrow1 - mn1);
            float sum0 = 0.0f, sum1 = 0.0f;
#pragma unroll
            for (int nf = 0; nf < 8; ++nf) {
                sa[nf][0] = __expf(sa[nf][0] - mn0);
                sa[nf][1] = __expf(sa[nf][1] - mn0);
                sa[nf][2] = __expf(sa[nf][2] - mn1);
                sa[nf][3] = __expf(sa[nf][3] - mn1);
                sum0 += sa[nf][0] + sa[nf][1];
                sum1 += sa[nf][2] + sa[nf][3];
            }
            sum0 += __shfl_xor_sync(0xffffffffu, sum0, 1);
            sum0 += __shfl_xor_sync(0xffffffffu, sum0, 2);
            sum1 += __shfl_xor_sync(0xffffffffu, sum1, 1);
            sum1 += __shfl_xor_sync(0xffffffffu, sum1, 2);
            lrow0 = lrow0 * corr0 + sum0;
            lrow1 = lrow1 * corr1 + sum1;
            mrow0 = mn0; mrow1 = mn1;
#pragma unroll
            for (int nf = 0; nf < 8; ++nf) {
                oacc[nf][0] *= corr0; oacc[nf][1] *= corr0;
                oacc[nf][2] *= corr1; oacc[nf][3] *= corr1;
            }

            // ---- pack P c-frags -> fp16 A-frags (hi/lo) ----
            uint32_t pah[4][4], pal[4][4];
#pragma unroll
            for (int ks = 0; ks < 4; ++ks) {
                pack_hl_f16(sa[2 * ks][0],     sa[2 * ks][1],     pah[ks][0], pal[ks][0]);
                pack_hl_f16(sa[2 * ks][2],     sa[2 * ks][3],     pah[ks][1], pal[ks][1]);
                pack_hl_f16(sa[2 * ks + 1][0], sa[2 * ks + 1][1], pah[ks][2], pal[ks][2]);
                pack_hl_f16(sa[2 * ks + 1][2], sa[2 * ks + 1][3], pah[ks][3], pal[ks][3]);
            }

            // ---- O += P V (fp16 2-term); V b-frags via ldmatrix.trans ----
            const uint32_t vh_base = stg + AT_KTILE_B + (v_row * APITCH) * 2;
#pragma unroll
            for (int nf = 0; nf < 8; ++nf) {
#pragma unroll
                for (int ks = 0; ks < 4; ++ks) {
                    uint32_t Bh[2];
                    uint32_t off = (ks * 16 * APITCH + nf * 8) * 2;
                    LDSM_X2_T(Bh[0], Bh[1], vh_base + off);
                    mma_fp16(oacc[nf], pah[ks], Bh);
                    mma_fp16(oacc[nf], pal[ks], Bh);
                }
            }
        }
        __syncthreads();
        if (kt + 2 < nkt) { load_kv(kt + 2); CP_COMMIT(); }
    }

    // ---- epilogue: normalize and write y fp16 hi/lo ----
    const float inv0 = 1.0f / lrow0, inv1 = 1.0f / lrow1;
    const int rg0 = q0 + wid * 16 + rloc;
    const size_t y0 = ((size_t)(b * TT) + rg0) * CC + h * DD;
    const size_t y1 = y0 + 8 * CC;
#pragma unroll
    for (int nf = 0; nf < 8; ++nf) {
        int col = nf * 8 + 2 * (lid & 3);
        uint32_t h01, l01, h23, l23;
        pack_hl_f16(oacc[nf][0] * inv0, oacc[nf][1] * inv0, h01, l01);
        pack_hl_f16(oacc[nf][2] * inv1, oacc[nf][3] * inv1, h23, l23);
        *(uint32_t*)&yhi[y0 + col] = h01;
        *(uint32_t*)&ylo[y0 + col] = l01;
        *(uint32_t*)&yhi[y1 + col] = h23;
        *(uint32_t*)&ylo[y1 + col] = l23;
    }
}

// ---------------------------------------------------------------------------
// Launch
// ---------------------------------------------------------------------------
extern "C" void kernel_launch(void* const* d_in, const int* in_sizes, int n_in,
                              void* d_out, int out_size)
{
    const float* x     = (const float*)d_in[0];
    const float* wqkv  = (const float*)d_in[1];
    const float* bqkv  = (const float*)d_in[2];
    const float* wproj = (const float*)d_in[3];
    const float* bproj = (const float*)d_in[4];
    float* out = (float*)d_out;

    __half *qkh, *qkl, *xh, *xl, *wqh, *wph, *yh, *yl;
    cudaGetSymbolAddress((void**)&qkh, g_qkv_hi);
    cudaGetSymbolAddress((void**)&qkl, g_qkv_lo);
    cudaGetSymbolAddress((void**)&xh,  g_x_hi);
    cudaGetSymbolAddress((void**)&xl,  g_x_lo);
    cudaGetSymbolAddress((void**)&wqh, g_wq_hi);
    cudaGetSymbolAddress((void**)&wph, g_wp_hi);
    cudaGetSymbolAddress((void**)&yh,  g_y_hi);
    cudaGetSymbolAddress((void**)&yl,  g_y_lo);

    cudaFuncSetAttribute(mma_gemm_kernel,
                         cudaFuncAttributeMaxDynamicSharedMemorySize, GEMM_SMEM);
    cudaFuncSetAttribute(attn_mma_kernel,
                         cudaFuncAttributeMaxDynamicSharedMemorySize, AT_SMEM);

    // Prep: split x (fp16); transpose both weight matrices to fp16
    split_f16_kernel<<<(M_ROWS * CC / 4 + 255) / 256, 256>>>(x, xh, xl, M_ROWS * CC / 4);
    transpose_f16_kernel<<<dim3(N_QKV / 32, CC / 32), dim3(32, 8)>>>(wqkv, wqh, CC, N_QKV);
    transpose_f16_kernel<<<dim3(CC / 32, CC / 32), dim3(32, 8)>>>(wproj, wph, CC, CC);

    // 1) qkv = x @ Wqkv + b -> fp16 hi (+lo for Q cols), Q pre-scaled 2^-3
    mma_gemm_kernel<<<dim3(N_QKV / 128, M_ROWS / 128), 256, GEMM_SMEM>>>(
        xh, xl, wqh, bqkv, nullptr, qkh, qkl, CC, M_ROWS, N_QKV, CC);

    // 2) fp16 HMMA causal flash attention -> y fp16 hi/lo
    attn_mma_kernel<<<dim3(TT / 128, BB * HH), 256, AT_SMEM>>>(qkh, qkl, yh, yl);

    // 3) out = y @ Wproj + b  (fp32 output)
    mma_gemm_kernel<<<dim3(CC / 128, M_ROWS / 128), 256, GEMM_SMEM>>>(
        yh, yl, wph, bproj, out, nullptr, nullptr, 0, M_ROWS, CC, CC);
}

// round 17
// speedup vs baseline: 5.0900x; 1.3327x over previous
#include <cuda_runtime.h>
#include <cuda_bf16.h>
#include <cuda_fp16.h>
#include <cstdint>
#include <math.h>

// Problem constants
#define BB 8
#define TT 1024
#define CC 768
#define HH 12
#define DD 64
#define M_ROWS (BB * TT)          // 8192
#define N_QKV  (3 * CC)           // 2304

// ---------------------------------------------------------------------------
// Scratch (device globals; runtime allocation is forbidden)
// ---------------------------------------------------------------------------
__device__ __half g_qkv_hi[M_ROWS * N_QKV];   // GEMM1 out (fp16)
__device__ __half g_qkv_lo[M_ROWS * N_QKV];   // lo written for Q cols only
__device__ __half g_x_hi[M_ROWS * CC];        // x (fp16, single)
__device__ __half g_wq_hi[N_QKV * CC];        // Wqkv^T fp16
__device__ __half g_wp_hi[CC * CC];           // Wproj^T fp16
__device__ __half g_y_hi[M_ROWS * CC];        // attention out (fp16, single)

// ---------------------------------------------------------------------------
// Portable tensor-core helpers: mma.sync + ldmatrix + cp.async
// ---------------------------------------------------------------------------
__device__ __forceinline__ uint32_t smem_u32(const void* p) {
    uint32_t a;
    asm("{ .reg .u64 t; cvta.to.shared.u64 t, %1; cvt.u32.u64 %0, t; }"
        : "=r"(a) : "l"(p));
    return a;
}

#define CP_ASYNC16(dst, src) \
    asm volatile("cp.async.cg.shared.global [%0], [%1], 16;" \
                 :: "r"(dst), "l"(src) : "memory")
#define CP_COMMIT() asm volatile("cp.async.commit_group;" ::: "memory")
#define CP_WAIT(n)  asm volatile("cp.async.wait_group %0;" :: "n"(n) : "memory")

#define LDSM_X4(r0, r1, r2, r3, addr) \
    asm volatile("ldmatrix.sync.aligned.m8n8.x4.shared.b16 {%0,%1,%2,%3}, [%4];" \
                 : "=r"(r0), "=r"(r1), "=r"(r2), "=r"(r3) : "r"(addr))
#define LDSM_X2(r0, r1, addr) \
    asm volatile("ldmatrix.sync.aligned.m8n8.x2.shared.b16 {%0,%1}, [%2];" \
                 : "=r"(r0), "=r"(r1) : "r"(addr))
#define LDSM_X2_T(r0, r1, addr) \
    asm volatile("ldmatrix.sync.aligned.m8n8.x2.trans.shared.b16 {%0,%1}, [%2];" \
                 : "=r"(r0), "=r"(r1) : "r"(addr))

__device__ __forceinline__ void mma_fp16(float* c, const uint32_t* a, const uint32_t* b) {
    asm volatile(
        "mma.sync.aligned.m16n8k16.row.col.f32.f16.f16.f32 "
        "{%0,%1,%2,%3}, {%4,%5,%6,%7}, {%8,%9}, {%0,%1,%2,%3};"
        : "+f"(c[0]), "+f"(c[1]), "+f"(c[2]), "+f"(c[3])
        : "r"(a[0]), "r"(a[1]), "r"(a[2]), "r"(a[3]), "r"(b[0]), "r"(b[1]));
}

// fp32 pair -> packed fp16x2 hi + lo
__device__ __forceinline__ void pack_hl_f16(float a, float b, uint32_t& hi, uint32_t& lo) {
    __half h0 = __float2half(a);
    __half h1 = __float2half(b);
    __half l0 = __float2half(a - __half2float(h0));
    __half l1 = __float2half(b - __half2float(h1));
    __half2 ph; ph.x = h0; ph.y = h1;
    __half2 pl; pl.x = l0; pl.y = l1;
    hi = *(uint32_t*)&ph;
    lo = *(uint32_t*)&pl;
}
// fp32 pair -> packed fp16x2 (hi only)
__device__ __forceinline__ uint32_t pack_f16(float a, float b) {
    __half2 p; p.x = __float2half(a); p.y = __float2half(b);
    return *(uint32_t*)&p;
}

// ---------------------------------------------------------------------------
// Single-term fp16 HMMA GEMM: C = A[M,K] @ W + bias (W transposed as B[N,K]).
// A and B single fp16 (err ~2.7e-4 each side). CTA 128x128, BK=64,
// 8 warps of 64x32, 3-stage cp.async, 2 CTAs/SM (221KB smem total).
// Output: fp32 (Cf) OR fp16 hi (+lo for first qcols cols, scaled 2^-3).
// ---------------------------------------------------------------------------
#define GP 72                             // fp16 elems per smem row (64 + 8)
#define GTILE_B (128 * GP * 2)            // 18432 bytes per tile
#define GSTAGE_B (2 * GTILE_B)            // A|B = 36864
#define GEMM_SMEM (3 * GSTAGE_B)          // 110592 (x2 CTAs = 221184)

__global__ void __launch_bounds__(256, 2)
mma_gemm_kernel(const __half* __restrict__ Ahi,
                const __half* __restrict__ Bhi,
                const float* __restrict__ bias,
                float* __restrict__ Cf,
                __half* __restrict__ Chi, __half* __restrict__ Clo,
                int qcols, int M, int N, int K)
{
    extern __shared__ char smem[];
    const uint32_t sb = smem_u32(smem);
    const int tid = threadIdx.x;
    const int wid = tid >> 5;
    const int lid = tid & 31;
    const int bm = blockIdx.y * 128;
    const int bn = blockIdx.x * 128;
    const int m0 = (wid >> 2) * 64;
    const int n0 = (wid & 3) * 32;
    const int NCH = K / 64;

    float acc[4][4][4];
#pragma unroll
    for (int i = 0; i < 4; i++)
#pragma unroll
        for (int j = 0; j < 4; j++)
#pragma unroll
            for (int r = 0; r < 4; r++) acc[i][j][r] = 0.0f;

    auto cp_tile = [&](const __half* g, int row0, int kc, uint32_t sdst) {
#pragma unroll
        for (int it = 0; it < 4; ++it) {
            int idx = tid + it * 256;     // 0..1023
            int r = idx >> 3;
            int u = idx & 7;
            const __half* src = g + (size_t)(row0 + r) * K + kc + u * 8;
            CP_ASYNC16(sdst + (r * GP + u * 8) * 2, src);
        }
    };
    auto load_stage = [&](int c, int stg) {
        uint32_t base = sb + stg * GSTAGE_B;
        int kc = c * 64;
        cp_tile(Ahi, bm, kc, base);
        cp_tile(Bhi, bn, kc, base + GTILE_B);
    };

    load_stage(0, 0);
    CP_COMMIT();
    load_stage(1, 1);
    CP_COMMIT();

    const int a_row = lid & 15;
    const int a_k   = lid >> 4;
    const int b_row = lid & 7;
    const int b_k   = (lid >> 3) & 1;

    for (int c = 0; c < NCH; ++c) {
        if (c + 2 < NCH) {
            load_stage(c + 2, (c + 2) % 3);
            CP_COMMIT();
            CP_WAIT(2);
        } else {
            CP_WAIT(0);
        }
        __syncthreads();

        const uint32_t base = sb + (c % 3) * GSTAGE_B;
        const uint32_t pa = base + ((m0 + a_row) * GP + a_k * 8) * 2;
        const uint32_t pb = base + GTILE_B + ((n0 + b_row) * GP + b_k * 8) * 2;

#pragma unroll
        for (int ks = 0; ks < 4; ++ks) {
            const uint32_t ko = ks * 32;  // 16 fp16 = 32 bytes per k-step
            uint32_t Bh[4][2];
#pragma unroll
            for (int nf = 0; nf < 4; ++nf)
                LDSM_X2(Bh[nf][0], Bh[nf][1], pb + ko + nf * (8 * GP * 2));
#pragma unroll
            for (int mf = 0; mf < 4; ++mf) {
                uint32_t Ah[4];
                LDSM_X4(Ah[0], Ah[1], Ah[2], Ah[3], pa + ko + mf * (16 * GP * 2));
#pragma unroll
                for (int nf = 0; nf < 4; ++nf) mma_fp16(acc[mf][nf], Ah, Bh[nf]);
            }
        }
        __syncthreads();
    }

    // Epilogue
    const int grow = lid >> 2;
    const int gcol = (lid & 3) * 2;
#pragma unroll
    for (int mf = 0; mf < 4; ++mf) {
#pragma unroll
        for (int nf = 0; nf < 4; ++nf) {
            int r0  = bm + m0 + mf * 16 + grow;
            int col = bn + n0 + nf * 8 + gcol;
            float b0 = bias[col], b1 = bias[col + 1];
            float v0 = acc[mf][nf][0] + b0, v1 = acc[mf][nf][1] + b1;
            float v2 = acc[mf][nf][2] + b0, v3 = acc[mf][nf][3] + b1;
            if (Cf) {
                *(float2*)&Cf[(size_t)r0 * N + col]       = make_float2(v0, v1);
                *(float2*)&Cf[(size_t)(r0 + 8) * N + col] = make_float2(v2, v3);
            } else {
                bool isq = (col < qcols);
                if (isq) { v0 *= 0.125f; v1 *= 0.125f; v2 *= 0.125f; v3 *= 0.125f; }
                uint32_t h01, l01, h23, l23;
                pack_hl_f16(v0, v1, h01, l01);
                pack_hl_f16(v2, v3, h23, l23);
                *(uint32_t*)&Chi[(size_t)r0 * N + col]       = h01;
                *(uint32_t*)&Chi[(size_t)(r0 + 8) * N + col] = h23;
                if (isq) {
                    *(uint32_t*)&Clo[(size_t)r0 * N + col]       = l01;
                    *(uint32_t*)&Clo[(size_t)(r0 + 8) * N + col] = l23;
                }
            }
        }
    }
}

// ---------------------------------------------------------------------------
// fp32 -> fp16 convert (x; single precision term), vectorized
// ---------------------------------------------------------------------------
__global__ void __launch_bounds__(256)
convert_f16_kernel(const float* __restrict__ in, __half* __restrict__ hi, int n4)
{
    int i = blockIdx.x * blockDim.x + threadIdx.x;
    if (i >= n4) return;
    float4 v = ((const float4*)in)[i];
    ((uint32_t*)hi)[2 * i]     = pack_f16(v.x, v.y);
    ((uint32_t*)hi)[2 * i + 1] = pack_f16(v.z, v.w);
}

// ---------------------------------------------------------------------------
// W[K][N] fp32 -> T[N][K] fp16 (tiled transpose)
// ---------------------------------------------------------------------------
__global__ void __launch_bounds__(256)
transpose_f16_kernel(const float* __restrict__ W, __half* __restrict__ Thi,
                     int K, int N)
{
    __shared__ float t[32][33];
    const int n0 = blockIdx.x * 32;
    const int k0 = blockIdx.y * 32;
    const int tx = threadIdx.x, ty = threadIdx.y;
#pragma unroll
    for (int j = 0; j < 4; ++j)
        t[ty + j * 8][tx] = W[(size_t)(k0 + ty + j * 8) * N + n0 + tx];
    __syncthreads();
#pragma unroll
    for (int j = 0; j < 4; ++j) {
        int n = n0 + ty + j * 8;
        int k = k0 + tx;
        Thi[(size_t)n * K + k] = __float2half(t[tx][ty + j * 8]);
    }
}

// ---------------------------------------------------------------------------
// fp16 HMMA causal flash attention, 2-term on both GEMMs:
//   S = Qhi K + Qlo K   (K single fp16)
//   O += Phi V + Plo V  (V single fp16)
// q-tile 128 (8 warps x 16 rows), k-tile 64, Q pre-scaled 2^-3 upstream.
// Outputs y as single fp16 (GEMM2 is single-A). APITCH=72 conflict-free.
// ---------------------------------------------------------------------------
#define APITCH 72
#define AT_QTILE_B (128 * APITCH * 2)    // 18432
#define AT_KTILE_B (64 * APITCH * 2)     // 9216
#define AT_STAGE_B (2 * AT_KTILE_B)      // 18432 (K|V)
#define AT_SMEM (2 * AT_QTILE_B + 2 * AT_STAGE_B)   // 73728

__global__ void __launch_bounds__(256, 1)
attn_mma_kernel(const __half* __restrict__ qvh,
                const __half* __restrict__ qvl,
                __half* __restrict__ yhi)
{
    extern __shared__ char smem[];
    const uint32_t sb = smem_u32(smem);
    const int tid = threadIdx.x, wid = tid >> 5, lid = tid & 31;
    const int qt = gridDim.x - 1 - blockIdx.x;   // heavy tiles launch first
    const int bh = blockIdx.y, b = bh / HH, h = bh % HH;
    const int q0 = qt * 128;
    const uint32_t sQh = sb, sQl = sb + AT_QTILE_B;
    const uint32_t sStage = sb + 2 * AT_QTILE_B;
    const size_t rowbase = (size_t)b * TT * N_QKV + h * DD;

    // Q tile load (hi/lo), 128 rows x 64 elems
#pragma unroll
    for (int it = 0; it < 4; ++it) {
        int idx = tid + it * 256;          // 0..1023
        int r = idx >> 3, u = idx & 7;
        size_t goff = rowbase + (size_t)(q0 + r) * N_QKV + u * 8;
        uint32_t d = (r * APITCH + u * 8) * 2;
        CP_ASYNC16(sQh + d, qvh + goff);
        CP_ASYNC16(sQl + d, qvl + goff);
    }

    auto load_kv = [&](int kt) {
        uint32_t base = sStage + (kt & 1) * AT_STAGE_B;
        int k0 = kt * 64;
#pragma unroll
        for (int it = 0; it < 4; ++it) {
            int idx = tid + it * 256;      // 0..1023
            int tile = idx >> 9, rem = idx & 511;   // tile 0=K, 1=V
            int r = rem >> 3, u = rem & 7;
            int coff = (tile == 0) ? CC : 2 * CC;
            const __half* src = qvh + rowbase + (size_t)(k0 + r) * N_QKV + coff + u * 8;
            CP_ASYNC16(base + tile * AT_KTILE_B + (r * APITCH + u * 8) * 2, src);
        }
    };

    const int nkt = 2 * qt + 2;
    load_kv(0);
    CP_COMMIT();
    load_kv(1);
    CP_COMMIT();
    CP_WAIT(1);
    __syncthreads();

    // hoist Q fragments (loop-invariant)
    uint32_t qfh[4][4], qfl[4][4];
    {
        const int a_row = lid & 15, a_k = lid >> 4;
        uint32_t ah = sQh + ((wid * 16 + a_row) * APITCH + a_k * 8) * 2;
        uint32_t al = sQl + ((wid * 16 + a_row) * APITCH + a_k * 8) * 2;
#pragma unroll
        for (int ks = 0; ks < 4; ++ks) {
            LDSM_X4(qfh[ks][0], qfh[ks][1], qfh[ks][2], qfh[ks][3], ah + ks * 32);
            LDSM_X4(qfl[ks][0], qfl[ks][1], qfl[ks][2], qfl[ks][3], al + ks * 32);
        }
    }

    float oacc[8][4];
#pragma unroll
    for (int nf = 0; nf < 8; ++nf)
#pragma unroll
        for (int r = 0; r < 4; ++r) oacc[nf][r] = 0.0f;
    float mrow0 = -1e30f, mrow1 = -1e30f, lrow0 = 0.0f, lrow1 = 0.0f;

    const int b_row = lid & 7, b_k = (lid >> 3) & 1;
    const int v_row = lid & 15;
    const int rloc  = lid >> 2;

    for (int kt = 0; kt < nkt; ++kt) {
        if (kt > 0) {
            if (kt + 1 < nkt) CP_WAIT(1); else CP_WAIT(0);
            __syncthreads();
        }
        const int k0 = kt * 64;
        const uint32_t stg = sStage + (kt & 1) * AT_STAGE_B;

        if (k0 <= q0 + wid * 16 + 15) {      // warp-uniform causal skip
            // ---- S = Q K^T (fp16 2-term) ----
            float sa[8][4];
#pragma unroll
            for (int nf = 0; nf < 8; ++nf)
#pragma unroll
                for (int r = 0; r < 4; ++r) sa[nf][r] = 0.0f;

            const uint32_t kh_base = stg + (b_row * APITCH + b_k * 8) * 2;
#pragma unroll
            for (int nf = 0; nf < 8; ++nf) {
                uint32_t oh = kh_base + nf * (8 * APITCH * 2);
#pragma unroll
                for (int ks = 0; ks < 4; ++ks) {
                    uint32_t Bh[2];
                    LDSM_X2(Bh[0], Bh[1], oh + ks * 32);
                    mma_fp16(sa[nf], qfh[ks], Bh);
                    mma_fp16(sa[nf], qfl[ks], Bh);
                }
            }

            const int rg0 = q0 + wid * 16 + rloc;
            const int rg1 = rg0 + 8;
            if (k0 + 63 > q0 + wid * 16) {   // diagonal tile: mask
#pragma unroll
                for (int nf = 0; nf < 8; ++nf) {
                    int c0 = k0 + nf * 8 + 2 * (lid & 3);
                    if (c0     > rg0) sa[nf][0] = -1e30f;
                    if (c0 + 1 > rg0) sa[nf][1] = -1e30f;
                    if (c0     > rg1) sa[nf][2] = -1e30f;
                    if (c0 + 1 > rg1) sa[nf][3] = -1e30f;
                }
            }

            // ---- online softmax (rows rloc, rloc+8; quad reduce) ----
            float mx0 = -1e30f, mx1 = -1e30f;
#pragma unroll
            for (int nf = 0; nf < 8; ++nf) {
                mx0 = fmaxf(mx0, fmaxf(sa[nf][0], sa[nf][1]));
                mx1 = fmaxf(mx1, fmaxf(sa[nf][2], sa[nf][3]));
            }
            mx0 = fmaxf(mx0, __shfl_xor_sync(0xffffffffu, mx0, 1));
            mx0 = fmaxf(mx0, __shfl_xor_sync(0xffffffffu, mx0, 2));
            mx1 = fmaxf(mx1, __shfl_xor_sync(0xffffffffu, mx1, 1));
            mx1 = fmaxf(mx1, __shfl_xor_sync(0xffffffffu, mx1, 2));
            float mn0 = fmaxf(mrow0, mx0), mn1 = fmaxf(mrow1, mx1);
            float corr0 = __expf(mrow0 - mn0), corr1 = __expf(mrow1 - mn1);
            float sum0 = 0.0f, sum1 = 0.0f;
#pragma unroll
            for (int nf = 0; nf < 8; ++nf) {
                sa[nf][0] = __expf(sa[nf][0] - mn0);
                sa[nf][1] = __expf(sa[nf][1] - mn0);
                sa[nf][2] = __expf(sa[nf][2] - mn1);
                sa[nf][3] = __expf(sa[nf][3] - mn1);
                sum0 += sa[nf][0] + sa[nf][1];
                sum1 += sa[nf][2] + sa[nf][3];
            }
            sum0 += __shfl_xor_sync(0xffffffffu, sum0, 1);
            sum0 += __shfl_xor_sync(0xffffffffu, sum0, 2);
            sum1 += __shfl_xor_sync(0xffffffffu, sum1, 1);
            sum1 += __shfl_xor_sync(0xffffffffu, sum1, 2);
            lrow0 = lrow0 * corr0 + sum0;
            lrow1 = lrow1 * corr1 + sum1;
            mrow0 = mn0; mrow1 = mn1;
#pragma unroll
            for (int nf = 0; nf < 8; ++nf) {
                oacc[nf][0] *= corr0; oacc[nf][1] *= corr0;
                oacc[nf][2] *= corr1; oacc[nf][3] *= corr1;
            }

            // ---- pack P c-frags -> fp16 A-frags (hi/lo) ----
            uint32_t pah[4][4], pal[4][4];
#pragma unroll
            for (int ks = 0; ks < 4; ++ks) {
                pack_hl_f16(sa[2 * ks][0],     sa[2 * ks][1],     pah[ks][0], pal[ks][0]);
                pack_hl_f16(sa[2 * ks][2],     sa[2 * ks][3],     pah[ks][1], pal[ks][1]);
                pack_hl_f16(sa[2 * ks + 1][0], sa[2 * ks + 1][1], pah[ks][2], pal[ks][2]);
                pack_hl_f16(sa[2 * ks + 1][2], sa[2 * ks + 1][3], pah[ks][3], pal[ks][3]);
            }

            // ---- O += P V (fp16 2-term); V b-frags via ldmatrix.trans ----
            const uint32_t vh_base = stg + AT_KTILE_B + (v_row * APITCH) * 2;
#pragma unroll
            for (int nf = 0; nf < 8; ++nf) {
#pragma unroll
                for (int ks = 0; ks < 4; ++ks) {
                    uint32_t Bh[2];
                    uint32_t off = (ks * 16 * APITCH + nf * 8) * 2;
                    LDSM_X2_T(Bh[0], Bh[1], vh_base + off);
                    mma_fp16(oacc[nf], pah[ks], Bh);
                    mma_fp16(oacc[nf], pal[ks], Bh);
                }
            }
        }
        __syncthreads();
        if (kt + 2 < nkt) { load_kv(kt + 2); CP_COMMIT(); }
    }

    // ---- epilogue: normalize and write y fp16 ----
    const float inv0 = 1.0f / lrow0, inv1 = 1.0f / lrow1;
    const int rg0 = q0 + wid * 16 + rloc;
    const size_t y0 = ((size_t)(b * TT) + rg0) * CC + h * DD;
    const size_t y1 = y0 + 8 * CC;
#pragma unroll
    for (int nf = 0; nf < 8; ++nf) {
        int col = nf * 8 + 2 * (lid & 3);
        *(uint32_t*)&yhi[y0 + col] = pack_f16(oacc[nf][0] * inv0, oacc[nf][1] * inv0);
        *(uint32_t*)&yhi[y1 + col] = pack_f16(oacc[nf][2] * inv1, oacc[nf][3] * inv1);
    }
}

// ---------------------------------------------------------------------------
// Launch
// ---------------------------------------------------------------------------
extern "C" void kernel_launch(void* const* d_in, const int* in_sizes, int n_in,
                              void* d_out, int out_size)
{
    const float* x     = (const float*)d_in[0];
    const float* wqkv  = (const float*)d_in[1];
    const float* bqkv  = (const float*)d_in[2];
    const float* wproj = (const float*)d_in[3];
    const float* bproj = (const float*)d_in[4];
    float* out = (float*)d_out;

    __half *qkh, *qkl, *xh, *wqh, *wph, *yh;
    cudaGetSymbolAddress((void**)&qkh, g_qkv_hi);
    cudaGetSymbolAddress((void**)&qkl, g_qkv_lo);
    cudaGetSymbolAddress((void**)&xh,  g_x_hi);
    cudaGetSymbolAddress((void**)&wqh, g_wq_hi);
    cudaGetSymbolAddress((void**)&wph, g_wp_hi);
    cudaGetSymbolAddress((void**)&yh,  g_y_hi);

    cudaFuncSetAttribute(mma_gemm_kernel,
                         cudaFuncAttributeMaxDynamicSharedMemorySize, GEMM_SMEM);
    cudaFuncSetAttribute(attn_mma_kernel,
                         cudaFuncAttributeMaxDynamicSharedMemorySize, AT_SMEM);

    // Prep: convert x to fp16; transpose both weight matrices to fp16
    convert_f16_kernel<<<(M_ROWS * CC / 4 + 255) / 256, 256>>>(x, xh, M_ROWS * CC / 4);
    transpose_f16_kernel<<<dim3(N_QKV / 32, CC / 32), dim3(32, 8)>>>(wqkv, wqh, CC, N_QKV);
    transpose_f16_kernel<<<dim3(CC / 32, CC / 32), dim3(32, 8)>>>(wproj, wph, CC, CC);

    // 1) qkv = x @ Wqkv + b -> fp16 hi (+lo for Q cols), Q pre-scaled 2^-3
    mma_gemm_kernel<<<dim3(N_QKV / 128, M_ROWS / 128), 256, GEMM_SMEM>>>(
        xh, wqh, bqkv, nullptr, qkh, qkl, CC, M_ROWS, N_QKV, CC);

    // 2) fp16 HMMA causal flash attention -> y fp16
    attn_mma_kernel<<<dim3(TT / 128, BB * HH), 256, AT_SMEM>>>(qkh, qkl, yh);

    // 3) out = y @ Wproj + b  (fp32 output)
    mma_gemm_kernel<<<dim3(CC / 128, M_ROWS / 128), 256, GEMM_SMEM>>>(
        yh, wph, bproj, out, nullptr, nullptr, 0, M_ROWS, CC, CC);
}